// round 9
// baseline (speedup 1.0000x reference)
#include <cuda_runtime.h>
#include <cuda_bf16.h>
#include <math.h>
#include <stdint.h>

// ---------------- problem constants ----------------
#define BATCH   2
#define SEQ     2048
#define DMODEL  1024
#define NHEADS  16
#define DHEAD   64
#define FFDIM   4096
#define MTOK    (BATCH * SEQ)          // 4096 token rows
#define QKVN    (3 * DMODEL)           // 3072
#define QKVSTR  3072

// ---------------- scratch (device globals; no allocation) ----------------
__device__ float g_H   [MTOK * DMODEL];
__device__ float g_QKV [MTOK * QKVN];
__device__ float g_CTX [MTOK * DMODEL];
__device__ float g_X2  [MTOK * DMODEL];
__device__ float g_FF  [MTOK * FFDIM];
__device__ float g_Wqkv[QKVN  * DMODEL];
__device__ float g_Wo  [DMODEL * DMODEL];
__device__ float g_W1  [FFDIM * DMODEL];
__device__ float g_W2  [DMODEL * FFDIM];
__device__ float g_Bqkv[QKVN];

__device__ __forceinline__ uint32_t s2u(const void* p) {
    uint32_t a;
    asm("{ .reg .u64 t; cvta.to.shared.u64 t, %1; cvt.u32.u64 %0, t; }" : "=r"(a) : "l"(p));
    return a;
}
__device__ __forceinline__ uint32_t f2tf(float x) {
    uint32_t r; asm("cvt.rna.tf32.f32 %0, %1;" : "=r"(r) : "f"(x)); return r;
}
__device__ __forceinline__ void cp16(uint32_t dst, const void* src) {
    asm volatile("cp.async.cg.shared.global [%0], [%1], 16;" :: "r"(dst), "l"(src));
}
#define CP_COMMIT() asm volatile("cp.async.commit_group;" ::: "memory")
#define CP_WAIT(n)  asm volatile("cp.async.wait_group %0;" :: "n"(n) : "memory")

__device__ __forceinline__ void mma_tf32(float c[4], uint32_t a0, uint32_t a1,
                                         uint32_t a2, uint32_t a3,
                                         uint32_t b0, uint32_t b1)
{
    asm volatile(
        "mma.sync.aligned.m16n8k8.row.col.f32.tf32.tf32.f32 "
        "{%0,%1,%2,%3}, {%4,%5,%6,%7}, {%8,%9}, {%0,%1,%2,%3};"
        : "+f"(c[0]), "+f"(c[1]), "+f"(c[2]), "+f"(c[3])
        : "r"(a0), "r"(a1), "r"(a2), "r"(a3), "r"(b0), "r"(b1));
}

// =======================================================================
// fused weight transpose + tf32 round: one launch for all 6 matrices.
// out[n][k] = tf32(in[k][n]); in is [K][N] row-major.
// tile ranges: [0,4096) 1024x1024 x4 ; [4096,8192) w1 ; [8192,12288) w2
// =======================================================================
#define TRN_BLOCKS 12288

__global__ void transpose_all(const float* __restrict__ wq, const float* __restrict__ wk,
                              const float* __restrict__ wv, const float* __restrict__ wo,
                              const float* __restrict__ w1, const float* __restrict__ w2,
                              float* __restrict__ Wqkv, float* __restrict__ Wo,
                              float* __restrict__ W1,   float* __restrict__ W2)
{
    int bid = blockIdx.x;
    const float* src; float* dst; int K, N, local;
    if (bid < 4096) {
        int m = bid >> 10; local = bid & 1023; K = 1024; N = 1024;
        src = (m == 0) ? wq : (m == 1) ? wk : (m == 2) ? wv : wo;
        dst = (m == 3) ? Wo : Wqkv + m * 1024 * 1024;
    } else if (bid < 8192) {
        local = bid - 4096; K = 1024; N = 4096; src = w1; dst = W1;
    } else {
        local = bid - 8192; K = 4096; N = 1024; src = w2; dst = W2;
    }
    int tilesN = N >> 5;
    int n0 = (local % tilesN) * 32;
    int k0 = (local / tilesN) * 32;

    __shared__ float tile[32][33];
    int tx = threadIdx.x, ty = threadIdx.y;   // 32 x 8
    #pragma unroll
    for (int j = 0; j < 32; j += 8)
        tile[ty + j][tx] = src[(size_t)(k0 + ty + j) * N + n0 + tx];
    __syncthreads();
    #pragma unroll
    for (int j = 0; j < 32; j += 8)
        dst[(size_t)(n0 + ty + j) * K + k0 + tx] = __uint_as_float(f2tf(tile[tx][ty + j]));
}

__global__ void concat_bias(const float* __restrict__ a, const float* __restrict__ b,
                            const float* __restrict__ c, float* __restrict__ o)
{
    int i = blockIdx.x * blockDim.x + threadIdx.x;
    if (i < QKVN)
        o[i] = (i < DMODEL) ? a[i] : (i < 2 * DMODEL ? b[i - DMODEL] : c[i - 2 * DMODEL]);
}

// =======================================================================
// LayerNorm
// =======================================================================
__global__ void ln_kernel(const float* __restrict__ x,
                          const float* __restrict__ gamma,
                          const float* __restrict__ beta,
                          float* __restrict__ out)
{
    int row = blockIdx.x;
    int tid = threadIdx.x;
    const float* xr = x + (size_t)row * DMODEL;

    float4 v = *(const float4*)(xr + tid * 4);
    float s  = v.x + v.y + v.z + v.w;
    float sq = v.x*v.x + v.y*v.y + v.z*v.z + v.w*v.w;
    #pragma unroll
    for (int off = 16; off > 0; off >>= 1) {
        s  += __shfl_xor_sync(0xffffffffu, s,  off);
        sq += __shfl_xor_sync(0xffffffffu, sq, off);
    }
    __shared__ float ssum[8], ssq[8];
    int wid = tid >> 5, lane = tid & 31;
    if (lane == 0) { ssum[wid] = s; ssq[wid] = sq; }
    __syncthreads();
    float tot = 0.f, totq = 0.f;
    #pragma unroll
    for (int w = 0; w < 8; w++) { tot += ssum[w]; totq += ssq[w]; }

    const float invN = 1.0f / (float)DMODEL;
    float mean = tot * invN;
    float var  = totq * invN - mean * mean;
    float inv  = rsqrtf(var + 1e-5f);

    float4 g4 = *(const float4*)(gamma + tid * 4);
    float4 b4 = *(const float4*)(beta  + tid * 4);
    float4 o;
    o.x = (v.x - mean) * inv * g4.x + b4.x;
    o.y = (v.y - mean) * inv * g4.y + b4.y;
    o.z = (v.z - mean) * inv * g4.z + b4.z;
    o.w = (v.w - mean) * inv * g4.w + b4.w;
    *(float4*)(out + (size_t)row * DMODEL + tid * 4) = o;
}

// =======================================================================
// tf32 mma.sync GEMM (identical to round 8 — passing, ~134 TF/s)
// =======================================================================
#define BM 128
#define BN 256
#define BK 32
#define PAD 36
#define A_FLOATS (128 * PAD)
#define B_FLOATS (256 * PAD)
#define STG_FLOATS (A_FLOATS + B_FLOATS)
#define NSTAGE 4
#define GEMM_SMEM (NSTAGE * STG_FLOATS * 4)     // 221184 B

__global__ __launch_bounds__(256, 1)
void gemm_mma(const float* __restrict__ A, const float* __restrict__ Wt,
              const float* __restrict__ bias, const float* __restrict__ resid,
              float* __restrict__ C, int M, int N, int K, int relu)
{
    extern __shared__ float smem[];

    int tid  = threadIdx.x;
    int warp = tid >> 5, lane = tid & 31;
    int wm = warp >> 2;
    int wn = warp & 3;
    int g  = lane >> 2;
    int q  = lane & 3;
    int bm = blockIdx.y * BM;
    int bn = blockIdx.x * BN;

    int s_row = tid >> 3;
    int s_kq  = (tid & 7) * 4;

    const int KT = K / BK;

    auto stage = [&](int st, int kt) {
        float* As = smem + st * STG_FLOATS;
        float* Bs = As + A_FLOATS;
        uint32_t aBase = s2u(As);
        uint32_t bBase = s2u(Bs);
        const float* ag = A  + (size_t)(bm + s_row) * K + kt * BK + s_kq;
        const float* bg = Wt + (size_t)(bn + s_row) * K + kt * BK + s_kq;
        #pragma unroll
        for (int i = 0; i < 4; i++)
            cp16(aBase + ((s_row + i * 32) * PAD + s_kq) * 4, ag + (size_t)(i * 32) * K);
        #pragma unroll
        for (int i = 0; i < 8; i++)
            cp16(bBase + ((s_row + i * 32) * PAD + s_kq) * 4, bg + (size_t)(i * 32) * K);
    };

    float c[4][8][4];
    #pragma unroll
    for (int mi = 0; mi < 4; mi++)
        #pragma unroll
        for (int ni = 0; ni < 8; ni++)
            #pragma unroll
            for (int r = 0; r < 4; r++) c[mi][ni][r] = 0.f;

    stage(0, 0); CP_COMMIT();
    stage(1, 1); CP_COMMIT();
    stage(2, 2); CP_COMMIT();

    for (int kt = 0; kt < KT; kt++) {
        CP_WAIT(2);
        __syncthreads();

        if (kt + 3 < KT) stage((kt + 3) & 3, kt + 3);
        CP_COMMIT();

        const float* Af = smem + (kt & 3) * STG_FLOATS + (wm * 64 + g) * PAD + q;
        const float* Bf = smem + (kt & 3) * STG_FLOATS + A_FLOATS + (wn * 64 + g) * PAD + q;
        #pragma unroll
        for (int ks = 0; ks < 4; ks++) {
            uint32_t a[4][4], b[8][2];
            #pragma unroll
            for (int mi = 0; mi < 4; mi++) {
                const float* p = Af + mi * 16 * PAD + ks * 8;
                a[mi][0] = __float_as_uint(p[0]);
                a[mi][1] = __float_as_uint(p[8 * PAD]);
                a[mi][2] = __float_as_uint(p[4]);
                a[mi][3] = __float_as_uint(p[8 * PAD + 4]);
            }
            #pragma unroll
            for (int ni = 0; ni < 8; ni++) {
                const float* p = Bf + ni * 8 * PAD + ks * 8;
                b[ni][0] = __float_as_uint(p[0]);
                b[ni][1] = __float_as_uint(p[4]);
            }
            #pragma unroll
            for (int mi = 0; mi < 4; mi++)
                #pragma unroll
                for (int ni = 0; ni < 8; ni++)
                    mma_tf32(c[mi][ni], a[mi][0], a[mi][1], a[mi][2], a[mi][3],
                             b[ni][0], b[ni][1]);
        }
    }

    #pragma unroll
    for (int ni = 0; ni < 8; ni++) {
        int col = bn + wn * 64 + ni * 8 + q * 2;
        float2 bv = *(const float2*)(bias + col);
        #pragma unroll
        for (int mi = 0; mi < 4; mi++) {
            int row = bm + wm * 64 + mi * 16 + g;
            #pragma unroll
            for (int half = 0; half < 2; half++) {
                int r = row + half * 8;
                float2 o;
                o.x = c[mi][ni][half * 2 + 0] + bv.x;
                o.y = c[mi][ni][half * 2 + 1] + bv.y;
                if (resid) {
                    float2 rv = *(const float2*)(resid + (size_t)r * N + col);
                    o.x += rv.x; o.y += rv.y;
                }
                if (relu) { o.x = fmaxf(o.x, 0.f); o.y = fmaxf(o.y, 0.f); }
                *(float2*)(C + (size_t)r * N + col) = o;
            }
        }
    }
}

// =======================================================================
// tf32 tensor-core flash attention — double-buffered K/V/mask,
// ONE barrier per key tile, next-tile loads overlapped with mma.
// =======================================================================
#define APAD 68
#define NEG_BIG (-1e30f)
#define NT (SEQ / 64)
// Qs[128][68] + 2x Ks[64][68] + 2x Vt[64][68] + 2x msk[64]
#define ATTN_SMEM ((128 + 4 * 64) * APAD * 4 + 2 * 64 * 4)

__global__ __launch_bounds__(256, 1)
void attn_mma(const float* __restrict__ QKV, const int* __restrict__ mask,
              float* __restrict__ O)
{
    extern __shared__ float sm[];
    float* Qs  = sm;                         // [128][APAD]
    float* KsB = Qs + 128 * APAD;            // 2 x [64][APAD]
    float* VtB = KsB + 2 * 64 * APAD;        // 2 x [64][APAD]
    int*   mskB = (int*)(VtB + 2 * 64 * APAD); // 2 x [64]

    int tid  = threadIdx.x;
    int warp = tid >> 5, lane = tid & 31;
    int g = lane >> 2, q = lane & 3;
    int row0 = warp * 16;
    int q0 = blockIdx.x * 128;
    int h  = blockIdx.y;
    int b  = blockIdx.z;

    // V/K staging thread map
    int key = tid >> 2;            // 0..63
    int db  = (tid & 3) * 16;      // 0,16,32,48

    // ---- stage Q (scale folded; exact power of 2) ----
    {
        int r  = tid >> 1;
        int c0 = (tid & 1) * 32;
        const float* qp = QKV + (size_t)(b*SEQ + q0 + r) * QKVSTR + h*DHEAD + c0;
        float* qd = &Qs[r * APAD + c0];
        #pragma unroll
        for (int i = 0; i < 8; i++) {
            float4 v = *(const float4*)(qp + i * 4);
            qd[i*4+0] = __uint_as_float(f2tf(v.x * 0.125f));
            qd[i*4+1] = __uint_as_float(f2tf(v.y * 0.125f));
            qd[i*4+2] = __uint_as_float(f2tf(v.z * 0.125f));
            qd[i*4+3] = __uint_as_float(f2tf(v.w * 0.125f));
        }
    }

    // ---- prologue: tile 0 into buffer 0 ----
    {
        const float* kp = QKV + (size_t)(b*SEQ + key) * QKVSTR + DMODEL + h*DHEAD;
        uint32_t kd = s2u(&KsB[key * APAD]);
        #pragma unroll
        for (int i = 0; i < 4; i++)
            cp16(kd + (db + i * 4) * 4, kp + db + i * 4);
        CP_COMMIT();
        const float* vp = QKV + (size_t)(b*SEQ + key) * QKVSTR + 2*DMODEL + h*DHEAD + db;
        #pragma unroll
        for (int i = 0; i < 4; i++) {
            float4 v = *(const float4*)(vp + i * 4);
            VtB[(db + i*4 + 0) * APAD + key] = __uint_as_float(f2tf(v.x));
            VtB[(db + i*4 + 1) * APAD + key] = __uint_as_float(f2tf(v.y));
            VtB[(db + i*4 + 2) * APAD + key] = __uint_as_float(f2tf(v.z));
            VtB[(db + i*4 + 3) * APAD + key] = __uint_as_float(f2tf(v.w));
        }
        if (tid < 64) mskB[tid] = mask[b*SEQ + tid];
    }

    float m_r[2] = {NEG_BIG, NEG_BIG};
    float l_r[2] = {0.f, 0.f};
    float o[8][4];
    #pragma unroll
    for (int nv = 0; nv < 8; nv++)
        #pragma unroll
        for (int r = 0; r < 4; r++) o[nv][r] = 0.f;

    int base = lane & ~3;
    float vreg[16];
    int mreg = 0;

    for (int t = 0; t < NT; t++) {
        int cur = t & 1, nxt = cur ^ 1;
        CP_WAIT(0);               // K(t) complete (only group outstanding)
        __syncthreads();          // V(t)/msk(t) stores visible; buffers nxt free

        bool hn = (t + 1 < NT);
        if (hn) {
            int t0n = (t + 1) * 64;
            // issue next K (cp.async, overlaps compute below)
            const float* kp = QKV + (size_t)(b*SEQ + t0n + key) * QKVSTR + DMODEL + h*DHEAD;
            uint32_t kd = s2u(&KsB[nxt * 64 * APAD + key * APAD]);
            #pragma unroll
            for (int i = 0; i < 4; i++)
                cp16(kd + (db + i * 4) * 4, kp + db + i * 4);
            CP_COMMIT();
            // issue next V loads into registers (latency hides under QK mma)
            const float* vp = QKV + (size_t)(b*SEQ + t0n + key) * QKVSTR + 2*DMODEL + h*DHEAD + db;
            #pragma unroll
            for (int i = 0; i < 4; i++)
                *(float4*)(vreg + i * 4) = *(const float4*)(vp + i * 4);
            if (tid < 64) mreg = mask[b*SEQ + t0n + tid];
        }

        // ---- S = Q @ K^T from buffer cur ----
        const float* KsC = KsB + cur * 64 * APAD;
        float sc[8][4];
        #pragma unroll
        for (int nj = 0; nj < 8; nj++)
            #pragma unroll
            for (int r = 0; r < 4; r++) sc[nj][r] = 0.f;

        #pragma unroll
        for (int ks = 0; ks < 8; ks++) {
            const float* ap = &Qs[(row0 + g) * APAD + ks * 8 + q];
            uint32_t a0 = __float_as_uint(ap[0]);
            uint32_t a1 = __float_as_uint(ap[8 * APAD]);
            uint32_t a2 = __float_as_uint(ap[4]);
            uint32_t a3 = __float_as_uint(ap[8 * APAD + 4]);
            #pragma unroll
            for (int nj = 0; nj < 8; nj++) {
                const float* bp = &KsC[(nj * 8 + g) * APAD + ks * 8 + q];
                mma_tf32(sc[nj], a0, a1, a2, a3,
                         __float_as_uint(bp[0]), __float_as_uint(bp[4]));
            }
        }

        // ---- mask (buffer cur) ----
        const int* mskC = mskB + cur * 64;
        #pragma unroll
        for (int nj = 0; nj < 8; nj++) {
            int c0 = nj * 8 + 2 * q;
            if (mskC[c0]     == 0) { sc[nj][0] = NEG_BIG; sc[nj][2] = NEG_BIG; }
            if (mskC[c0 + 1] == 0) { sc[nj][1] = NEG_BIG; sc[nj][3] = NEG_BIG; }
        }

        // ---- online softmax ----
        float mx0 = NEG_BIG, mx1 = NEG_BIG;
        #pragma unroll
        for (int nj = 0; nj < 8; nj++) {
            mx0 = fmaxf(mx0, fmaxf(sc[nj][0], sc[nj][1]));
            mx1 = fmaxf(mx1, fmaxf(sc[nj][2], sc[nj][3]));
        }
        mx0 = fmaxf(mx0, __shfl_xor_sync(0xffffffffu, mx0, 1));
        mx0 = fmaxf(mx0, __shfl_xor_sync(0xffffffffu, mx0, 2));
        mx1 = fmaxf(mx1, __shfl_xor_sync(0xffffffffu, mx1, 1));
        mx1 = fmaxf(mx1, __shfl_xor_sync(0xffffffffu, mx1, 2));
        float mn0 = fmaxf(m_r[0], mx0);
        float mn1 = fmaxf(m_r[1], mx1);
        float fac0 = __expf(m_r[0] - mn0);
        float fac1 = __expf(m_r[1] - mn1);

        float sum0 = 0.f, sum1 = 0.f;
        #pragma unroll
        for (int nj = 0; nj < 8; nj++) {
            sc[nj][0] = __expf(sc[nj][0] - mn0);
            sc[nj][1] = __expf(sc[nj][1] - mn0);
            sc[nj][2] = __expf(sc[nj][2] - mn1);
            sc[nj][3] = __expf(sc[nj][3] - mn1);
            sum0 += sc[nj][0] + sc[nj][1];
            sum1 += sc[nj][2] + sc[nj][3];
        }
        sum0 += __shfl_xor_sync(0xffffffffu, sum0, 1);
        sum0 += __shfl_xor_sync(0xffffffffu, sum0, 2);
        sum1 += __shfl_xor_sync(0xffffffffu, sum1, 1);
        sum1 += __shfl_xor_sync(0xffffffffu, sum1, 2);

        l_r[0] = l_r[0] * fac0 + sum0;  m_r[0] = mn0;
        l_r[1] = l_r[1] * fac1 + sum1;  m_r[1] = mn1;

        #pragma unroll
        for (int nv = 0; nv < 8; nv++) {
            o[nv][0] *= fac0; o[nv][1] *= fac0;
            o[nv][2] *= fac1; o[nv][3] *= fac1;
        }

        // ---- store next V (loads landed during QK mma) ----
        if (hn) {
            float* VtN = VtB + nxt * 64 * APAD;
            #pragma unroll
            for (int i = 0; i < 16; i++)
                VtN[(db + i) * APAD + key] = __uint_as_float(f2tf(vreg[i]));
            if (tid < 64) mskB[nxt * 64 + tid] = mreg;
        }

        // ---- O += P @ V from buffer cur ----
        const float* VtC = VtB + cur * 64 * APAD;
        #pragma unroll
        for (int ks = 0; ks < 8; ks++) {
            int sl = base | (q >> 1);
            int sh = base | ((q >> 1) + 2);
            float vl0 = __shfl_sync(0xffffffffu, sc[ks][0], sl);
            float vh0 = __shfl_sync(0xffffffffu, sc[ks][1], sl);
            float ul0 = __shfl_sync(0xffffffffu, sc[ks][0], sh);
            float uh0 = __shfl_sync(0xffffffffu, sc[ks][1], sh);
            float vl1 = __shfl_sync(0xffffffffu, sc[ks][2], sl);
            float vh1 = __shfl_sync(0xffffffffu, sc[ks][3], sl);
            float ul1 = __shfl_sync(0xffffffffu, sc[ks][2], sh);
            float uh1 = __shfl_sync(0xffffffffu, sc[ks][3], sh);
            uint32_t A0 = f2tf((q & 1) ? vh0 : vl0);
            uint32_t A2 = f2tf((q & 1) ? uh0 : ul0);
            uint32_t A1 = f2tf((q & 1) ? vh1 : vl1);
            uint32_t A3 = f2tf((q & 1) ? uh1 : ul1);
            #pragma unroll
            for (int nv = 0; nv < 8; nv++) {
                const float* bp = &VtC[(nv * 8 + g) * APAD + ks * 8 + q];
                mma_tf32(o[nv], A0, A1, A2, A3,
                         __float_as_uint(bp[0]), __float_as_uint(bp[4]));
            }
        }
    }

    float inv0 = 1.0f / l_r[0];
    float inv1 = 1.0f / l_r[1];
    int r0 = q0 + row0 + g;
    int r1 = r0 + 8;
    #pragma unroll
    for (int nv = 0; nv < 8; nv++) {
        int col = h * DHEAD + nv * 8 + 2 * q;
        float2 w0, w1;
        w0.x = o[nv][0] * inv0; w0.y = o[nv][1] * inv0;
        w1.x = o[nv][2] * inv1; w1.y = o[nv][3] * inv1;
        *(float2*)(O + (size_t)(b*SEQ + r0) * DMODEL + col) = w0;
        *(float2*)(O + (size_t)(b*SEQ + r1) * DMODEL + col) = w1;
    }
}

// =======================================================================
// launch
// =======================================================================
extern "C" void kernel_launch(void* const* d_in, const int* in_sizes, int n_in,
                              void* d_out, int out_size)
{
    const float* x     = (const float*)d_in[0];
    const int*   mask  = (const int*)  d_in[1];
    const float* wq    = (const float*)d_in[2];
    const float* bq    = (const float*)d_in[3];
    const float* wk    = (const float*)d_in[4];
    const float* bk    = (const float*)d_in[5];
    const float* wv    = (const float*)d_in[6];
    const float* bv    = (const float*)d_in[7];
    const float* wo    = (const float*)d_in[8];
    const float* bo    = (const float*)d_in[9];
    const float* ln1_g = (const float*)d_in[10];
    const float* ln1_b = (const float*)d_in[11];
    const float* ln2_g = (const float*)d_in[12];
    const float* ln2_b = (const float*)d_in[13];
    const float* w1    = (const float*)d_in[14];
    const float* b1    = (const float*)d_in[15];
    const float* w2    = (const float*)d_in[16];
    const float* b2    = (const float*)d_in[17];
    float* out = (float*)d_out;

    float *H, *QKV, *CTX, *X2, *FF, *Wqkv, *Wo, *W1, *W2, *Bqkv;
    cudaGetSymbolAddress((void**)&H,    g_H);
    cudaGetSymbolAddress((void**)&QKV,  g_QKV);
    cudaGetSymbolAddress((void**)&CTX,  g_CTX);
    cudaGetSymbolAddress((void**)&X2,   g_X2);
    cudaGetSymbolAddress((void**)&FF,   g_FF);
    cudaGetSymbolAddress((void**)&Wqkv, g_Wqkv);
    cudaGetSymbolAddress((void**)&Wo,   g_Wo);
    cudaGetSymbolAddress((void**)&W1,   g_W1);
    cudaGetSymbolAddress((void**)&W2,   g_W2);
    cudaGetSymbolAddress((void**)&Bqkv, g_Bqkv);

    cudaFuncSetAttribute(gemm_mma, cudaFuncAttributeMaxDynamicSharedMemorySize, GEMM_SMEM);
    cudaFuncSetAttribute(attn_mma, cudaFuncAttributeMaxDynamicSharedMemorySize, ATTN_SMEM);

    // weight preprocessing: one fused launch + bias concat
    transpose_all<<<TRN_BLOCKS, dim3(32, 8)>>>(wq, wk, wv, wo, w1, w2, Wqkv, Wo, W1, W2);
    concat_bias<<<QKVN/256, 256>>>(bq, bk, bv, Bqkv);

    // residual 1: pre-LN attention
    ln_kernel<<<MTOK, 256>>>(x, ln1_g, ln1_b, H);
    gemm_mma<<<dim3(QKVN/BN, MTOK/BM), 256, GEMM_SMEM>>>(H, Wqkv, Bqkv, nullptr, QKV,
                                                         MTOK, QKVN, DMODEL, 0);
    attn_mma<<<dim3(SEQ/128, NHEADS, BATCH), 256, ATTN_SMEM>>>(QKV, mask, CTX);
    gemm_mma<<<dim3(DMODEL/BN, MTOK/BM), 256, GEMM_SMEM>>>(CTX, Wo, bo, x, X2,
                                                           MTOK, DMODEL, DMODEL, 0);

    // residual 2: pre-LN feed-forward
    ln_kernel<<<MTOK, 256>>>(X2, ln2_g, ln2_b, H);
    gemm_mma<<<dim3(FFDIM/BN, MTOK/BM), 256, GEMM_SMEM>>>(H, W1, b1, nullptr, FF,
                                                          MTOK, FFDIM, DMODEL, 1);
    gemm_mma<<<dim3(DMODEL/BN, MTOK/BM), 256, GEMM_SMEM>>>(FF, W2, b2, X2, out,
                                                           MTOK, DMODEL, FFDIM, 0);
}

// round 11
// speedup vs baseline: 1.0347x; 1.0347x over previous
#include <cuda_runtime.h>
#include <cuda_bf16.h>
#include <math.h>
#include <stdint.h>

// ---------------- problem constants ----------------
#define BATCH   2
#define SEQ     2048
#define DMODEL  1024
#define NHEADS  16
#define DHEAD   64
#define FFDIM   4096
#define MTOK    (BATCH * SEQ)          // 4096 token rows
#define QKVN    (3 * DMODEL)           // 3072
#define QKVSTR  3072

// ---------------- scratch (device globals; no allocation) ----------------
__device__ float g_H   [MTOK * DMODEL];
__device__ float g_QKV [MTOK * QKVN];
__device__ float g_CTX [MTOK * DMODEL];
__device__ float g_X2  [MTOK * DMODEL];
__device__ float g_FF  [MTOK * FFDIM];
__device__ float g_Wqkv[QKVN  * DMODEL];
__device__ float g_Wo  [DMODEL * DMODEL];
__device__ float g_W1  [FFDIM * DMODEL];
__device__ float g_W2  [DMODEL * FFDIM];
__device__ float g_Bqkv[QKVN];

__device__ __forceinline__ uint32_t s2u(const void* p) {
    uint32_t a;
    asm("{ .reg .u64 t; cvta.to.shared.u64 t, %1; cvt.u32.u64 %0, t; }" : "=r"(a) : "l"(p));
    return a;
}
__device__ __forceinline__ uint32_t f2tf(float x) {
    uint32_t r; asm("cvt.rna.tf32.f32 %0, %1;" : "=r"(r) : "f"(x)); return r;
}
__device__ __forceinline__ void cp16(uint32_t dst, const void* src) {
    asm volatile("cp.async.cg.shared.global [%0], [%1], 16;" :: "r"(dst), "l"(src));
}
#define CP_COMMIT() asm volatile("cp.async.commit_group;" ::: "memory")
#define CP_WAIT(n)  asm volatile("cp.async.wait_group %0;" :: "n"(n) : "memory")

__device__ __forceinline__ void mma_tf32(float c[4], uint32_t a0, uint32_t a1,
                                         uint32_t a2, uint32_t a3,
                                         uint32_t b0, uint32_t b1)
{
    asm volatile(
        "mma.sync.aligned.m16n8k8.row.col.f32.tf32.tf32.f32 "
        "{%0,%1,%2,%3}, {%4,%5,%6,%7}, {%8,%9}, {%0,%1,%2,%3};"
        : "+f"(c[0]), "+f"(c[1]), "+f"(c[2]), "+f"(c[3])
        : "r"(a0), "r"(a1), "r"(a2), "r"(a3), "r"(b0), "r"(b1));
}

// =======================================================================
// weight transpose + tf32 round (round-8 version)
// =======================================================================
__global__ void transpose_tf32(const float* __restrict__ in, float* __restrict__ out,
                               int K, int N)
{
    __shared__ float tile[32][33];
    int n0 = blockIdx.x * 32, k0 = blockIdx.y * 32;
    int tx = threadIdx.x, ty = threadIdx.y;
    #pragma unroll
    for (int j = 0; j < 32; j += 8)
        tile[ty + j][tx] = in[(size_t)(k0 + ty + j) * N + n0 + tx];
    __syncthreads();
    #pragma unroll
    for (int j = 0; j < 32; j += 8)
        out[(size_t)(n0 + ty + j) * K + k0 + tx] = __uint_as_float(f2tf(tile[tx][ty + j]));
}

__global__ void concat_bias(const float* __restrict__ a, const float* __restrict__ b,
                            const float* __restrict__ c, float* __restrict__ o)
{
    int i = blockIdx.x * blockDim.x + threadIdx.x;
    if (i < QKVN)
        o[i] = (i < DMODEL) ? a[i] : (i < 2 * DMODEL ? b[i - DMODEL] : c[i - 2 * DMODEL]);
}

// =======================================================================
// LayerNorm
// =======================================================================
__global__ void ln_kernel(const float* __restrict__ x,
                          const float* __restrict__ gamma,
                          const float* __restrict__ beta,
                          float* __restrict__ out)
{
    int row = blockIdx.x;
    int tid = threadIdx.x;
    const float* xr = x + (size_t)row * DMODEL;

    float4 v = *(const float4*)(xr + tid * 4);
    float s  = v.x + v.y + v.z + v.w;
    float sq = v.x*v.x + v.y*v.y + v.z*v.z + v.w*v.w;
    #pragma unroll
    for (int off = 16; off > 0; off >>= 1) {
        s  += __shfl_xor_sync(0xffffffffu, s,  off);
        sq += __shfl_xor_sync(0xffffffffu, sq, off);
    }
    __shared__ float ssum[8], ssq[8];
    int wid = tid >> 5, lane = tid & 31;
    if (lane == 0) { ssum[wid] = s; ssq[wid] = sq; }
    __syncthreads();
    float tot = 0.f, totq = 0.f;
    #pragma unroll
    for (int w = 0; w < 8; w++) { tot += ssum[w]; totq += ssq[w]; }

    const float invN = 1.0f / (float)DMODEL;
    float mean = tot * invN;
    float var  = totq * invN - mean * mean;
    float inv  = rsqrtf(var + 1e-5f);

    float4 g4 = *(const float4*)(gamma + tid * 4);
    float4 b4 = *(const float4*)(beta  + tid * 4);
    float4 o;
    o.x = (v.x - mean) * inv * g4.x + b4.x;
    o.y = (v.y - mean) * inv * g4.y + b4.y;
    o.z = (v.z - mean) * inv * g4.z + b4.z;
    o.w = (v.w - mean) * inv * g4.w + b4.w;
    *(float4*)(out + (size_t)row * DMODEL + tid * 4) = o;
}

// =======================================================================
// tf32 mma.sync GEMM: C[M,N] = A[M,K] @ Wt[N,K]^T + bias (+resid)(relu)
// block tile 128x128, BK=32; 8 warps 2x4; warp tile 64x32 (mi=4, ni=4).
// 3-stage cp.async pipeline, ONE __syncthreads per K-iteration.
// smem 110592 B -> 2 CTAs/SM (occupancy doubled vs round 8).
// =======================================================================
#define BM 128
#define BN 128
#define BK 32
#define PAD 36
#define A_FLOATS (128 * PAD)
#define B_FLOATS (128 * PAD)
#define STG_FLOATS (A_FLOATS + B_FLOATS)        // 9216 floats
#define NSTAGE 3
#define GEMM_SMEM (NSTAGE * STG_FLOATS * 4)     // 110592 B

__global__ __launch_bounds__(256, 2)
void gemm_mma(const float* __restrict__ A, const float* __restrict__ Wt,
              const float* __restrict__ bias, const float* __restrict__ resid,
              float* __restrict__ C, int M, int N, int K, int relu)
{
    extern __shared__ float smem[];

    int tid  = threadIdx.x;
    int warp = tid >> 5, lane = tid & 31;
    int wm = warp >> 2;          // 0..1 -> 64-row group
    int wn = warp & 3;           // 0..3 -> 32-col group
    int g  = lane >> 2;          // 0..7
    int q  = lane & 3;           // 0..3
    int bm = blockIdx.y * BM;
    int bn = blockIdx.x * BN;

    int s_row = tid >> 3;              // 0..31 (+32*i)
    int s_kq  = (tid & 7) * 4;         // 0,4,...,28

    const int KT = K / BK;

    auto stage = [&](int st, int kt) {
        float* As = smem + st * STG_FLOATS;
        float* Bs = As + A_FLOATS;
        uint32_t aBase = s2u(As);
        uint32_t bBase = s2u(Bs);
        const float* ag = A  + (size_t)(bm + s_row) * K + kt * BK + s_kq;
        const float* bg = Wt + (size_t)(bn + s_row) * K + kt * BK + s_kq;
        #pragma unroll
        for (int i = 0; i < 4; i++) {
            cp16(aBase + ((s_row + i * 32) * PAD + s_kq) * 4, ag + (size_t)(i * 32) * K);
            cp16(bBase + ((s_row + i * 32) * PAD + s_kq) * 4, bg + (size_t)(i * 32) * K);
        }
    };

    float c[4][4][4];
    #pragma unroll
    for (int mi = 0; mi < 4; mi++)
        #pragma unroll
        for (int ni = 0; ni < 4; ni++)
            #pragma unroll
            for (int r = 0; r < 4; r++) c[mi][ni][r] = 0.f;

    // prologue: stages 0..1
    stage(0, 0); CP_COMMIT();
    stage(1, 1); CP_COMMIT();

    int st = 0;
    for (int kt = 0; kt < KT; kt++) {
        CP_WAIT(1);               // stage kt complete (1 younger group in flight)
        __syncthreads();          // all warps done reading recycled buffer

        if (kt + 2 < KT) stage((st + 2) % NSTAGE, kt + 2);
        CP_COMMIT();              // possibly-empty commit keeps accounting

        const float* Af = smem + st * STG_FLOATS + (wm * 64 + g) * PAD + q;
        const float* Bf = smem + st * STG_FLOATS + A_FLOATS + (wn * 32 + g) * PAD + q;
        #pragma unroll
        for (int ks = 0; ks < 4; ks++) {
            uint32_t a[4][4], b[4][2];
            #pragma unroll
            for (int mi = 0; mi < 4; mi++) {
                const float* p = Af + mi * 16 * PAD + ks * 8;
                a[mi][0] = __float_as_uint(p[0]);
                a[mi][1] = __float_as_uint(p[8 * PAD]);
                a[mi][2] = __float_as_uint(p[4]);
                a[mi][3] = __float_as_uint(p[8 * PAD + 4]);
            }
            #pragma unroll
            for (int ni = 0; ni < 4; ni++) {
                const float* p = Bf + ni * 8 * PAD + ks * 8;
                b[ni][0] = __float_as_uint(p[0]);
                b[ni][1] = __float_as_uint(p[4]);
            }
            #pragma unroll
            for (int mi = 0; mi < 4; mi++)
                #pragma unroll
                for (int ni = 0; ni < 4; ni++)
                    mma_tf32(c[mi][ni], a[mi][0], a[mi][1], a[mi][2], a[mi][3],
                             b[ni][0], b[ni][1]);
        }
        st = (st + 1) % NSTAGE;
    }

    // ---- epilogue ----
    #pragma unroll
    for (int ni = 0; ni < 4; ni++) {
        int col = bn + wn * 32 + ni * 8 + q * 2;
        float2 bv = *(const float2*)(bias + col);
        #pragma unroll
        for (int mi = 0; mi < 4; mi++) {
            int row = bm + wm * 64 + mi * 16 + g;
            #pragma unroll
            for (int half = 0; half < 2; half++) {
                int r = row + half * 8;
                float2 o;
                o.x = c[mi][ni][half * 2 + 0] + bv.x;
                o.y = c[mi][ni][half * 2 + 1] + bv.y;
                if (resid) {
                    float2 rv = *(const float2*)(resid + (size_t)r * N + col);
                    o.x += rv.x; o.y += rv.y;
                }
                if (relu) { o.x = fmaxf(o.x, 0.f); o.y = fmaxf(o.y, 0.f); }
                *(float2*)(C + (size_t)r * N + col) = o;
            }
        }
    }
}

// =======================================================================
// tf32 tensor-core flash attention (round-8 version — passing, 1174us total)
// =======================================================================
#define APAD 68
#define NEG_BIG (-1e30f)
#define ATTN_SMEM ((128 + 64 + 64) * APAD * 4 + 64 * 4)

__global__ __launch_bounds__(256, 1)
void attn_mma(const float* __restrict__ QKV, const int* __restrict__ mask,
              float* __restrict__ O)
{
    extern __shared__ float sm[];
    float* Qs = sm;                        // [128][APAD]
    float* Ks = Qs + 128 * APAD;           // [64][APAD]
    float* Vt = Ks + 64 * APAD;            // [64][APAD]
    int*   msk = (int*)(Vt + 64 * APAD);   // [64]

    int tid  = threadIdx.x;
    int warp = tid >> 5, lane = tid & 31;
    int g = lane >> 2, q = lane & 3;
    int row0 = warp * 16;
    int q0 = blockIdx.x * 128;
    int h  = blockIdx.y;
    int b  = blockIdx.z;

    {
        int r  = tid >> 1;
        int c0 = (tid & 1) * 32;
        const float* qp = QKV + (size_t)(b*SEQ + q0 + r) * QKVSTR + h*DHEAD + c0;
        float* qd = &Qs[r * APAD + c0];
        #pragma unroll
        for (int i = 0; i < 8; i++) {
            float4 v = *(const float4*)(qp + i * 4);
            qd[i*4+0] = __uint_as_float(f2tf(v.x * 0.125f));
            qd[i*4+1] = __uint_as_float(f2tf(v.y * 0.125f));
            qd[i*4+2] = __uint_as_float(f2tf(v.z * 0.125f));
            qd[i*4+3] = __uint_as_float(f2tf(v.w * 0.125f));
        }
    }

    float m_r[2] = {NEG_BIG, NEG_BIG};
    float l_r[2] = {0.f, 0.f};
    float o[8][4];
    #pragma unroll
    for (int nv = 0; nv < 8; nv++)
        #pragma unroll
        for (int r = 0; r < 4; r++) o[nv][r] = 0.f;

    int base = lane & ~3;

    for (int t0 = 0; t0 < SEQ; t0 += 64) {
        {
            int key = tid >> 2;
            int cb  = (tid & 3) * 16;
            const float* kp = QKV + (size_t)(b*SEQ + t0 + key) * QKVSTR + DMODEL + h*DHEAD;
            uint32_t kd = s2u(&Ks[key * APAD]);
            #pragma unroll
            for (int i = 0; i < 4; i++)
                cp16(kd + (cb + i * 4) * 4, kp + cb + i * 4);
        }
        CP_COMMIT();
        {
            int key = tid >> 2;
            int db  = (tid & 3) * 16;
            const float* vp = QKV + (size_t)(b*SEQ + t0 + key) * QKVSTR + 2*DMODEL + h*DHEAD + db;
            #pragma unroll
            for (int i = 0; i < 4; i++) {
                float4 v = *(const float4*)(vp + i * 4);
                Vt[(db + i*4 + 0) * APAD + key] = __uint_as_float(f2tf(v.x));
                Vt[(db + i*4 + 1) * APAD + key] = __uint_as_float(f2tf(v.y));
                Vt[(db + i*4 + 2) * APAD + key] = __uint_as_float(f2tf(v.z));
                Vt[(db + i*4 + 3) * APAD + key] = __uint_as_float(f2tf(v.w));
            }
        }
        if (tid < 64) msk[tid] = mask[b*SEQ + t0 + tid];
        CP_WAIT(0);
        __syncthreads();

        float sc[8][4];
        #pragma unroll
        for (int nj = 0; nj < 8; nj++)
            #pragma unroll
            for (int r = 0; r < 4; r++) sc[nj][r] = 0.f;

        #pragma unroll
        for (int ks = 0; ks < 8; ks++) {
            const float* ap = &Qs[(row0 + g) * APAD + ks * 8 + q];
            uint32_t a0 = __float_as_uint(ap[0]);
            uint32_t a1 = __float_as_uint(ap[8 * APAD]);
            uint32_t a2 = __float_as_uint(ap[4]);
            uint32_t a3 = __float_as_uint(ap[8 * APAD + 4]);
            #pragma unroll
            for (int nj = 0; nj < 8; nj++) {
                const float* bp = &Ks[(nj * 8 + g) * APAD + ks * 8 + q];
                mma_tf32(sc[nj], a0, a1, a2, a3,
                         __float_as_uint(bp[0]), __float_as_uint(bp[4]));
            }
        }

        #pragma unroll
        for (int nj = 0; nj < 8; nj++) {
            int c0 = nj * 8 + 2 * q;
            if (msk[c0]     == 0) { sc[nj][0] = NEG_BIG; sc[nj][2] = NEG_BIG; }
            if (msk[c0 + 1] == 0) { sc[nj][1] = NEG_BIG; sc[nj][3] = NEG_BIG; }
        }

        float mx0 = NEG_BIG, mx1 = NEG_BIG;
        #pragma unroll
        for (int nj = 0; nj < 8; nj++) {
            mx0 = fmaxf(mx0, fmaxf(sc[nj][0], sc[nj][1]));
            mx1 = fmaxf(mx1, fmaxf(sc[nj][2], sc[nj][3]));
        }
        mx0 = fmaxf(mx0, __shfl_xor_sync(0xffffffffu, mx0, 1));
        mx0 = fmaxf(mx0, __shfl_xor_sync(0xffffffffu, mx0, 2));
        mx1 = fmaxf(mx1, __shfl_xor_sync(0xffffffffu, mx1, 1));
        mx1 = fmaxf(mx1, __shfl_xor_sync(0xffffffffu, mx1, 2));
        float mn0 = fmaxf(m_r[0], mx0);
        float mn1 = fmaxf(m_r[1], mx1);
        float fac0 = __expf(m_r[0] - mn0);
        float fac1 = __expf(m_r[1] - mn1);

        float sum0 = 0.f, sum1 = 0.f;
        #pragma unroll
        for (int nj = 0; nj < 8; nj++) {
            sc[nj][0] = __expf(sc[nj][0] - mn0);
            sc[nj][1] = __expf(sc[nj][1] - mn0);
            sc[nj][2] = __expf(sc[nj][2] - mn1);
            sc[nj][3] = __expf(sc[nj][3] - mn1);
            sum0 += sc[nj][0] + sc[nj][1];
            sum1 += sc[nj][2] + sc[nj][3];
        }
        sum0 += __shfl_xor_sync(0xffffffffu, sum0, 1);
        sum0 += __shfl_xor_sync(0xffffffffu, sum0, 2);
        sum1 += __shfl_xor_sync(0xffffffffu, sum1, 1);
        sum1 += __shfl_xor_sync(0xffffffffu, sum1, 2);

        l_r[0] = l_r[0] * fac0 + sum0;  m_r[0] = mn0;
        l_r[1] = l_r[1] * fac1 + sum1;  m_r[1] = mn1;

        #pragma unroll
        for (int nv = 0; nv < 8; nv++) {
            o[nv][0] *= fac0; o[nv][1] *= fac0;
            o[nv][2] *= fac1; o[nv][3] *= fac1;
        }

        #pragma unroll
        for (int ks = 0; ks < 8; ks++) {
            int sl = base | (q >> 1);
            int sh = base | ((q >> 1) + 2);
            float vl0 = __shfl_sync(0xffffffffu, sc[ks][0], sl);
            float vh0 = __shfl_sync(0xffffffffu, sc[ks][1], sl);
            float ul0 = __shfl_sync(0xffffffffu, sc[ks][0], sh);
            float uh0 = __shfl_sync(0xffffffffu, sc[ks][1], sh);
            float vl1 = __shfl_sync(0xffffffffu, sc[ks][2], sl);
            float vh1 = __shfl_sync(0xffffffffu, sc[ks][3], sl);
            float ul1 = __shfl_sync(0xffffffffu, sc[ks][2], sh);
            float uh1 = __shfl_sync(0xffffffffu, sc[ks][3], sh);
            uint32_t A0 = f2tf((q & 1) ? vh0 : vl0);
            uint32_t A2 = f2tf((q & 1) ? uh0 : ul0);
            uint32_t A1 = f2tf((q & 1) ? vh1 : vl1);
            uint32_t A3 = f2tf((q & 1) ? uh1 : ul1);
            #pragma unroll
            for (int nv = 0; nv < 8; nv++) {
                const float* bp = &Vt[(nv * 8 + g) * APAD + ks * 8 + q];
                mma_tf32(o[nv], A0, A1, A2, A3,
                         __float_as_uint(bp[0]), __float_as_uint(bp[4]));
            }
        }
        __syncthreads();
    }

    float inv0 = 1.0f / l_r[0];
    float inv1 = 1.0f / l_r[1];
    int r0 = q0 + row0 + g;
    int r1 = r0 + 8;
    #pragma unroll
    for (int nv = 0; nv < 8; nv++) {
        int col = h * DHEAD + nv * 8 + 2 * q;
        float2 w0, w1;
        w0.x = o[nv][0] * inv0; w0.y = o[nv][1] * inv0;
        w1.x = o[nv][2] * inv1; w1.y = o[nv][3] * inv1;
        *(float2*)(O + (size_t)(b*SEQ + r0) * DMODEL + col) = w0;
        *(float2*)(O + (size_t)(b*SEQ + r1) * DMODEL + col) = w1;
    }
}

// =======================================================================
// launch
// =======================================================================
extern "C" void kernel_launch(void* const* d_in, const int* in_sizes, int n_in,
                              void* d_out, int out_size)
{
    const float* x     = (const float*)d_in[0];
    const int*   mask  = (const int*)  d_in[1];
    const float* wq    = (const float*)d_in[2];
    const float* bq    = (const float*)d_in[3];
    const float* wk    = (const float*)d_in[4];
    const float* bk    = (const float*)d_in[5];
    const float* wv    = (const float*)d_in[6];
    const float* bv    = (const float*)d_in[7];
    const float* wo    = (const float*)d_in[8];
    const float* bo    = (const float*)d_in[9];
    const float* ln1_g = (const float*)d_in[10];
    const float* ln1_b = (const float*)d_in[11];
    const float* ln2_g = (const float*)d_in[12];
    const float* ln2_b = (const float*)d_in[13];
    const float* w1    = (const float*)d_in[14];
    const float* b1    = (const float*)d_in[15];
    const float* w2    = (const float*)d_in[16];
    const float* b2    = (const float*)d_in[17];
    float* out = (float*)d_out;

    float *H, *QKV, *CTX, *X2, *FF, *Wqkv, *Wo, *W1, *W2, *Bqkv;
    cudaGetSymbolAddress((void**)&H,    g_H);
    cudaGetSymbolAddress((void**)&QKV,  g_QKV);
    cudaGetSymbolAddress((void**)&CTX,  g_CTX);
    cudaGetSymbolAddress((void**)&X2,   g_X2);
    cudaGetSymbolAddress((void**)&FF,   g_FF);
    cudaGetSymbolAddress((void**)&Wqkv, g_Wqkv);
    cudaGetSymbolAddress((void**)&Wo,   g_Wo);
    cudaGetSymbolAddress((void**)&W1,   g_W1);
    cudaGetSymbolAddress((void**)&W2,   g_W2);
    cudaGetSymbolAddress((void**)&Bqkv, g_Bqkv);

    cudaFuncSetAttribute(gemm_mma, cudaFuncAttributeMaxDynamicSharedMemorySize, GEMM_SMEM);
    cudaFuncSetAttribute(attn_mma, cudaFuncAttributeMaxDynamicSharedMemorySize, ATTN_SMEM);

    dim3 tb(32, 8);
    transpose_tf32<<<dim3(DMODEL/32, DMODEL/32), tb>>>(wq, Wqkv,                   DMODEL, DMODEL);
    transpose_tf32<<<dim3(DMODEL/32, DMODEL/32), tb>>>(wk, Wqkv + DMODEL*DMODEL,   DMODEL, DMODEL);
    transpose_tf32<<<dim3(DMODEL/32, DMODEL/32), tb>>>(wv, Wqkv + 2*DMODEL*DMODEL, DMODEL, DMODEL);
    transpose_tf32<<<dim3(DMODEL/32, DMODEL/32), tb>>>(wo, Wo, DMODEL, DMODEL);
    transpose_tf32<<<dim3(FFDIM/32,  DMODEL/32), tb>>>(w1, W1, DMODEL, FFDIM);
    transpose_tf32<<<dim3(DMODEL/32, FFDIM/32),  tb>>>(w2, W2, FFDIM, DMODEL);
    concat_bias<<<QKVN/256, 256>>>(bq, bk, bv, Bqkv);

    // residual 1: pre-LN attention
    ln_kernel<<<MTOK, 256>>>(x, ln1_g, ln1_b, H);
    gemm_mma<<<dim3(QKVN/BN, MTOK/BM), 256, GEMM_SMEM>>>(H, Wqkv, Bqkv, nullptr, QKV,
                                                         MTOK, QKVN, DMODEL, 0);
    attn_mma<<<dim3(SEQ/128, NHEADS, BATCH), 256, ATTN_SMEM>>>(QKV, mask, CTX);
    gemm_mma<<<dim3(DMODEL/BN, MTOK/BM), 256, GEMM_SMEM>>>(CTX, Wo, bo, x, X2,
                                                           MTOK, DMODEL, DMODEL, 0);

    // residual 2: pre-LN feed-forward
    ln_kernel<<<MTOK, 256>>>(X2, ln2_g, ln2_b, H);
    gemm_mma<<<dim3(FFDIM/BN, MTOK/BM), 256, GEMM_SMEM>>>(H, W1, b1, nullptr, FF,
                                                          MTOK, FFDIM, DMODEL, 1);
    gemm_mma<<<dim3(DMODEL/BN, MTOK/BM), 256, GEMM_SMEM>>>(FF, W2, b2, X2, out,
                                                           MTOK, DMODEL, FFDIM, 0);
}

// round 12
// speedup vs baseline: 1.3273x; 1.2828x over previous
#include <cuda_runtime.h>
#include <cuda_bf16.h>
#include <cuda_fp16.h>
#include <math.h>
#include <stdint.h>

// ---------------- problem constants ----------------
#define BATCH   2
#define SEQ     2048
#define DMODEL  1024
#define NHEADS  16
#define DHEAD   64
#define FFDIM   4096
#define MTOK    (BATCH * SEQ)          // 4096 token rows
#define QKVN    (3 * DMODEL)           // 3072
#define QKVSTR  3072

// ---------------- scratch (device globals; no allocation) ----------------
__device__ float g_H   [MTOK * DMODEL];
__device__ float g_QKV [MTOK * QKVN];
__device__ float g_CTX [MTOK * DMODEL];
__device__ float g_X2  [MTOK * DMODEL];
__device__ float g_FF  [MTOK * FFDIM];
// fp16 weights, transposed to [N][K] K-major
__device__ __half g_Wqkv[QKVN  * DMODEL];
__device__ __half g_Wo  [DMODEL * DMODEL];
__device__ __half g_W1  [FFDIM * DMODEL];
__device__ __half g_W2  [DMODEL * FFDIM];
__device__ float g_Bqkv[QKVN];

__device__ __forceinline__ uint32_t s2u(const void* p) {
    uint32_t a;
    asm("{ .reg .u64 t; cvta.to.shared.u64 t, %1; cvt.u32.u64 %0, t; }" : "=r"(a) : "l"(p));
    return a;
}
__device__ __forceinline__ uint32_t f2tf(float x) {
    uint32_t r; asm("cvt.rna.tf32.f32 %0, %1;" : "=r"(r) : "f"(x)); return r;
}
// pack two fp32 -> f16x2 {lo, hi}
__device__ __forceinline__ uint32_t f16x2(float lo, float hi) {
    uint32_t r; asm("cvt.rn.f16x2.f32 %0, %1, %2;" : "=r"(r) : "f"(hi), "f"(lo)); return r;
}
__device__ __forceinline__ void cp16(uint32_t dst, const void* src) {
    asm volatile("cp.async.cg.shared.global [%0], [%1], 16;" :: "r"(dst), "l"(src));
}
#define CP_COMMIT() asm volatile("cp.async.commit_group;" ::: "memory")
#define CP_WAIT(n)  asm volatile("cp.async.wait_group %0;" :: "n"(n) : "memory")

__device__ __forceinline__ void mma_tf32(float c[4], uint32_t a0, uint32_t a1,
                                         uint32_t a2, uint32_t a3,
                                         uint32_t b0, uint32_t b1)
{
    asm volatile(
        "mma.sync.aligned.m16n8k8.row.col.f32.tf32.tf32.f32 "
        "{%0,%1,%2,%3}, {%4,%5,%6,%7}, {%8,%9}, {%0,%1,%2,%3};"
        : "+f"(c[0]), "+f"(c[1]), "+f"(c[2]), "+f"(c[3])
        : "r"(a0), "r"(a1), "r"(a2), "r"(a3), "r"(b0), "r"(b1));
}

__device__ __forceinline__ void mma_f16(float c[4], uint32_t a0, uint32_t a1,
                                        uint32_t a2, uint32_t a3,
                                        uint32_t b0, uint32_t b1)
{
    asm volatile(
        "mma.sync.aligned.m16n8k16.row.col.f32.f16.f16.f32 "
        "{%0,%1,%2,%3}, {%4,%5,%6,%7}, {%8,%9}, {%0,%1,%2,%3};"
        : "+f"(c[0]), "+f"(c[1]), "+f"(c[2]), "+f"(c[3])
        : "r"(a0), "r"(a1), "r"(a2), "r"(a3), "r"(b0), "r"(b1));
}

// =======================================================================
// weight transpose + fp16 convert: out[n][k] = f16(in[k][n]); in is [K][N]
// =======================================================================
__global__ void transpose_half(const float* __restrict__ in, __half* __restrict__ out,
                               int K, int N)
{
    __shared__ float tile[32][33];
    int n0 = blockIdx.x * 32, k0 = blockIdx.y * 32;
    int tx = threadIdx.x, ty = threadIdx.y;
    #pragma unroll
    for (int j = 0; j < 32; j += 8)
        tile[ty + j][tx] = in[(size_t)(k0 + ty + j) * N + n0 + tx];
    __syncthreads();
    #pragma unroll
    for (int j = 0; j < 32; j += 8)
        out[(size_t)(n0 + ty + j) * K + k0 + tx] = __float2half_rn(tile[tx][ty + j]);
}

__global__ void concat_bias(const float* __restrict__ a, const float* __restrict__ b,
                            const float* __restrict__ c, float* __restrict__ o)
{
    int i = blockIdx.x * blockDim.x + threadIdx.x;
    if (i < QKVN)
        o[i] = (i < DMODEL) ? a[i] : (i < 2 * DMODEL ? b[i - DMODEL] : c[i - 2 * DMODEL]);
}

// =======================================================================
// LayerNorm
// =======================================================================
__global__ void ln_kernel(const float* __restrict__ x,
                          const float* __restrict__ gamma,
                          const float* __restrict__ beta,
                          float* __restrict__ out)
{
    int row = blockIdx.x;
    int tid = threadIdx.x;
    const float* xr = x + (size_t)row * DMODEL;

    float4 v = *(const float4*)(xr + tid * 4);
    float s  = v.x + v.y + v.z + v.w;
    float sq = v.x*v.x + v.y*v.y + v.z*v.z + v.w*v.w;
    #pragma unroll
    for (int off = 16; off > 0; off >>= 1) {
        s  += __shfl_xor_sync(0xffffffffu, s,  off);
        sq += __shfl_xor_sync(0xffffffffu, sq, off);
    }
    __shared__ float ssum[8], ssq[8];
    int wid = tid >> 5, lane = tid & 31;
    if (lane == 0) { ssum[wid] = s; ssq[wid] = sq; }
    __syncthreads();
    float tot = 0.f, totq = 0.f;
    #pragma unroll
    for (int w = 0; w < 8; w++) { tot += ssum[w]; totq += ssq[w]; }

    const float invN = 1.0f / (float)DMODEL;
    float mean = tot * invN;
    float var  = totq * invN - mean * mean;
    float inv  = rsqrtf(var + 1e-5f);

    float4 g4 = *(const float4*)(gamma + tid * 4);
    float4 b4 = *(const float4*)(beta  + tid * 4);
    float4 o;
    o.x = (v.x - mean) * inv * g4.x + b4.x;
    o.y = (v.y - mean) * inv * g4.y + b4.y;
    o.z = (v.z - mean) * inv * g4.z + b4.z;
    o.w = (v.w - mean) * inv * g4.w + b4.w;
    *(float4*)(out + (size_t)row * DMODEL + tid * 4) = o;
}

// =======================================================================
// fp16 mma.sync GEMM: C[M,N] = A[M,K] @ Wt[N,K]^T + bias (+resid)(relu)
// A fp32 (cvt to fp16 at fragment load), Wt fp16 [N][K].
// block 128x256, BK=32; 8 warps 2x4; warp tile 64x64 (mi=4, ni=8);
// m16n8k16 -> 32 mma per k16 step (half the instructions of tf32 path).
// 4-stage cp.async pipeline, ONE __syncthreads per K-iteration.
// PAD_A=40 floats, PAD_B=40 halves -> conflict-free fragment loads.
// =======================================================================
#define BM 128
#define BN 256
#define BK 32
#define PAD_A 40
#define PAD_B 40
#define A_STG_BYTES (128 * PAD_A * 4)       // 20480
#define B_STG_BYTES (256 * PAD_B * 2)       // 20480
#define STG_BYTES   (A_STG_BYTES + B_STG_BYTES)  // 40960
#define NSTAGE 4
#define GEMM_SMEM (NSTAGE * STG_BYTES)      // 163840 B

__global__ __launch_bounds__(256, 1)
void gemm_mma(const float* __restrict__ A, const __half* __restrict__ Wt,
              const float* __restrict__ bias, const float* __restrict__ resid,
              float* __restrict__ C, int M, int N, int K, int relu)
{
    extern __shared__ char smem_raw[];

    int tid  = threadIdx.x;
    int warp = tid >> 5, lane = tid & 31;
    int wm = warp >> 2;          // 0..1 -> 64-row group
    int wn = warp & 3;           // 0..3 -> 64-col group
    int g  = lane >> 2;          // 0..7
    int q  = lane & 3;           // 0..3
    int bm = blockIdx.y * BM;
    int bn = blockIdx.x * BN;

    // A staging: thread -> (row 0..31 (+32i), 4-float col)
    int s_rowA = tid >> 3;
    int s_kqA  = (tid & 7) * 4;
    // B staging: thread -> (row 0..63 (+64i), 8-half col)
    int s_rowB = tid >> 2;
    int s_kqB  = (tid & 3) * 8;

    const int KT = K / BK;

    auto stage = [&](int st, int kt) {
        uint32_t aBase = s2u(smem_raw + st * STG_BYTES);
        uint32_t bBase = aBase + A_STG_BYTES;
        const float*  ag = A  + (size_t)(bm + s_rowA) * K + kt * BK + s_kqA;
        const __half* bg = Wt + (size_t)(bn + s_rowB) * K + kt * BK + s_kqB;
        #pragma unroll
        for (int i = 0; i < 4; i++)   // A: 128 rows fp32
            cp16(aBase + ((s_rowA + i * 32) * PAD_A + s_kqA) * 4, ag + (size_t)(i * 32) * K);
        #pragma unroll
        for (int i = 0; i < 4; i++)   // B: 256 rows fp16
            cp16(bBase + ((s_rowB + i * 64) * PAD_B + s_kqB) * 2, bg + (size_t)(i * 64) * K);
    };

    float c[4][8][4];
    #pragma unroll
    for (int mi = 0; mi < 4; mi++)
        #pragma unroll
        for (int ni = 0; ni < 8; ni++)
            #pragma unroll
            for (int r = 0; r < 4; r++) c[mi][ni][r] = 0.f;

    stage(0, 0); CP_COMMIT();
    stage(1, 1); CP_COMMIT();
    stage(2, 2); CP_COMMIT();

    for (int kt = 0; kt < KT; kt++) {
        CP_WAIT(2);
        __syncthreads();

        if (kt + 3 < KT) stage((kt + 3) & 3, kt + 3);
        CP_COMMIT();

        const float*  Af = (const float*)(smem_raw + (kt & 3) * STG_BYTES)
                         + (wm * 64 + g) * PAD_A + 2 * q;
        const __half* Bf = (const __half*)(smem_raw + (kt & 3) * STG_BYTES + A_STG_BYTES)
                         + (wn * 64 + g) * PAD_B + 2 * q;

        #pragma unroll
        for (int ks = 0; ks < 2; ks++) {      // two k16 steps per BK=32
            uint32_t a[4][4], b[8][2];
            #pragma unroll
            for (int mi = 0; mi < 4; mi++) {
                const float* p = Af + mi * 16 * PAD_A + ks * 16;
                float2 f0 = *(const float2*)(p);                  // row g,   k=2q,2q+1
                float2 f1 = *(const float2*)(p + 8 * PAD_A);      // row g+8
                float2 f2 = *(const float2*)(p + 8);              // row g,   k=2q+8
                float2 f3 = *(const float2*)(p + 8 * PAD_A + 8);  // row g+8, k=2q+8
                a[mi][0] = f16x2(f0.x, f0.y);
                a[mi][1] = f16x2(f1.x, f1.y);
                a[mi][2] = f16x2(f2.x, f2.y);
                a[mi][3] = f16x2(f3.x, f3.y);
            }
            #pragma unroll
            for (int ni = 0; ni < 8; ni++) {
                const __half* p = Bf + ni * 8 * PAD_B + ks * 16;
                b[ni][0] = *(const uint32_t*)(p);        // k=2q,2q+1
                b[ni][1] = *(const uint32_t*)(p + 8);    // k=2q+8,2q+9
            }
            #pragma unroll
            for (int mi = 0; mi < 4; mi++)
                #pragma unroll
                for (int ni = 0; ni < 8; ni++)
                    mma_f16(c[mi][ni], a[mi][0], a[mi][1], a[mi][2], a[mi][3],
                            b[ni][0], b[ni][1]);
        }
    }

    // ---- epilogue (same C-frag mapping as 16808) ----
    #pragma unroll
    for (int ni = 0; ni < 8; ni++) {
        int col = bn + wn * 64 + ni * 8 + q * 2;
        float2 bv = *(const float2*)(bias + col);
        #pragma unroll
        for (int mi = 0; mi < 4; mi++) {
            int row = bm + wm * 64 + mi * 16 + g;
            #pragma unroll
            for (int half = 0; half < 2; half++) {
                int r = row + half * 8;
                float2 o;
                o.x = c[mi][ni][half * 2 + 0] + bv.x;
                o.y = c[mi][ni][half * 2 + 1] + bv.y;
                if (resid) {
                    float2 rv = *(const float2*)(resid + (size_t)r * N + col);
                    o.x += rv.x; o.y += rv.y;
                }
                if (relu) { o.x = fmaxf(o.x, 0.f); o.y = fmaxf(o.y, 0.f); }
                *(float2*)(C + (size_t)r * N + col) = o;
            }
        }
    }
}

// =======================================================================
// tf32 tensor-core flash attention (round-8 version — champion, untouched)
// =======================================================================
#define APAD 68
#define NEG_BIG (-1e30f)
#define ATTN_SMEM ((128 + 64 + 64) * APAD * 4 + 64 * 4)

__global__ __launch_bounds__(256, 1)
void attn_mma(const float* __restrict__ QKV, const int* __restrict__ mask,
              float* __restrict__ O)
{
    extern __shared__ float sm[];
    float* Qs = sm;                        // [128][APAD]
    float* Ks = Qs + 128 * APAD;           // [64][APAD]
    float* Vt = Ks + 64 * APAD;            // [64][APAD]
    int*   msk = (int*)(Vt + 64 * APAD);   // [64]

    int tid  = threadIdx.x;
    int warp = tid >> 5, lane = tid & 31;
    int g = lane >> 2, q = lane & 3;
    int row0 = warp * 16;
    int q0 = blockIdx.x * 128;
    int h  = blockIdx.y;
    int b  = blockIdx.z;

    {
        int r  = tid >> 1;
        int c0 = (tid & 1) * 32;
        const float* qp = QKV + (size_t)(b*SEQ + q0 + r) * QKVSTR + h*DHEAD + c0;
        float* qd = &Qs[r * APAD + c0];
        #pragma unroll
        for (int i = 0; i < 8; i++) {
            float4 v = *(const float4*)(qp + i * 4);
            qd[i*4+0] = __uint_as_float(f2tf(v.x * 0.125f));
            qd[i*4+1] = __uint_as_float(f2tf(v.y * 0.125f));
            qd[i*4+2] = __uint_as_float(f2tf(v.z * 0.125f));
            qd[i*4+3] = __uint_as_float(f2tf(v.w * 0.125f));
        }
    }

    float m_r[2] = {NEG_BIG, NEG_BIG};
    float l_r[2] = {0.f, 0.f};
    float o[8][4];
    #pragma unroll
    for (int nv = 0; nv < 8; nv++)
        #pragma unroll
        for (int r = 0; r < 4; r++) o[nv][r] = 0.f;

    int base = lane & ~3;

    for (int t0 = 0; t0 < SEQ; t0 += 64) {
        {
            int key = tid >> 2;
            int cb  = (tid & 3) * 16;
            const float* kp = QKV + (size_t)(b*SEQ + t0 + key) * QKVSTR + DMODEL + h*DHEAD;
            uint32_t kd = s2u(&Ks[key * APAD]);
            #pragma unroll
            for (int i = 0; i < 4; i++)
                cp16(kd + (cb + i * 4) * 4, kp + cb + i * 4);
        }
        CP_COMMIT();
        {
            int key = tid >> 2;
            int db  = (tid & 3) * 16;
            const float* vp = QKV + (size_t)(b*SEQ + t0 + key) * QKVSTR + 2*DMODEL + h*DHEAD + db;
            #pragma unroll
            for (int i = 0; i < 4; i++) {
                float4 v = *(const float4*)(vp + i * 4);
                Vt[(db + i*4 + 0) * APAD + key] = __uint_as_float(f2tf(v.x));
                Vt[(db + i*4 + 1) * APAD + key] = __uint_as_float(f2tf(v.y));
                Vt[(db + i*4 + 2) * APAD + key] = __uint_as_float(f2tf(v.z));
                Vt[(db + i*4 + 3) * APAD + key] = __uint_as_float(f2tf(v.w));
            }
        }
        if (tid < 64) msk[tid] = mask[b*SEQ + t0 + tid];
        CP_WAIT(0);
        __syncthreads();

        float sc[8][4];
        #pragma unroll
        for (int nj = 0; nj < 8; nj++)
            #pragma unroll
            for (int r = 0; r < 4; r++) sc[nj][r] = 0.f;

        #pragma unroll
        for (int ks = 0; ks < 8; ks++) {
            const float* ap = &Qs[(row0 + g) * APAD + ks * 8 + q];
            uint32_t a0 = __float_as_uint(ap[0]);
            uint32_t a1 = __float_as_uint(ap[8 * APAD]);
            uint32_t a2 = __float_as_uint(ap[4]);
            uint32_t a3 = __float_as_uint(ap[8 * APAD + 4]);
            #pragma unroll
            for (int nj = 0; nj < 8; nj++) {
                const float* bp = &Ks[(nj * 8 + g) * APAD + ks * 8 + q];
                mma_tf32(sc[nj], a0, a1, a2, a3,
                         __float_as_uint(bp[0]), __float_as_uint(bp[4]));
            }
        }

        #pragma unroll
        for (int nj = 0; nj < 8; nj++) {
            int c0 = nj * 8 + 2 * q;
            if (msk[c0]     == 0) { sc[nj][0] = NEG_BIG; sc[nj][2] = NEG_BIG; }
            if (msk[c0 + 1] == 0) { sc[nj][1] = NEG_BIG; sc[nj][3] = NEG_BIG; }
        }

        float mx0 = NEG_BIG, mx1 = NEG_BIG;
        #pragma unroll
        for (int nj = 0; nj < 8; nj++) {
            mx0 = fmaxf(mx0, fmaxf(sc[nj][0], sc[nj][1]));
            mx1 = fmaxf(mx1, fmaxf(sc[nj][2], sc[nj][3]));
        }
        mx0 = fmaxf(mx0, __shfl_xor_sync(0xffffffffu, mx0, 1));
        mx0 = fmaxf(mx0, __shfl_xor_sync(0xffffffffu, mx0, 2));
        mx1 = fmaxf(mx1, __shfl_xor_sync(0xffffffffu, mx1, 1));
        mx1 = fmaxf(mx1, __shfl_xor_sync(0xffffffffu, mx1, 2));
        float mn0 = fmaxf(m_r[0], mx0);
        float mn1 = fmaxf(m_r[1], mx1);
        float fac0 = __expf(m_r[0] - mn0);
        float fac1 = __expf(m_r[1] - mn1);

        float sum0 = 0.f, sum1 = 0.f;
        #pragma unroll
        for (int nj = 0; nj < 8; nj++) {
            sc[nj][0] = __expf(sc[nj][0] - mn0);
            sc[nj][1] = __expf(sc[nj][1] - mn0);
            sc[nj][2] = __expf(sc[nj][2] - mn1);
            sc[nj][3] = __expf(sc[nj][3] - mn1);
            sum0 += sc[nj][0] + sc[nj][1];
            sum1 += sc[nj][2] + sc[nj][3];
        }
        sum0 += __shfl_xor_sync(0xffffffffu, sum0, 1);
        sum0 += __shfl_xor_sync(0xffffffffu, sum0, 2);
        sum1 += __shfl_xor_sync(0xffffffffu, sum1, 1);
        sum1 += __shfl_xor_sync(0xffffffffu, sum1, 2);

        l_r[0] = l_r[0] * fac0 + sum0;  m_r[0] = mn0;
        l_r[1] = l_r[1] * fac1 + sum1;  m_r[1] = mn1;

        #pragma unroll
        for (int nv = 0; nv < 8; nv++) {
            o[nv][0] *= fac0; o[nv][1] *= fac0;
            o[nv][2] *= fac1; o[nv][3] *= fac1;
        }

        #pragma unroll
        for (int ks = 0; ks < 8; ks++) {
            int sl = base | (q >> 1);
            int sh = base | ((q >> 1) + 2);
            float vl0 = __shfl_sync(0xffffffffu, sc[ks][0], sl);
            float vh0 = __shfl_sync(0xffffffffu, sc[ks][1], sl);
            float ul0 = __shfl_sync(0xffffffffu, sc[ks][0], sh);
            float uh0 = __shfl_sync(0xffffffffu, sc[ks][1], sh);
            float vl1 = __shfl_sync(0xffffffffu, sc[ks][2], sl);
            float vh1 = __shfl_sync(0xffffffffu, sc[ks][3], sl);
            float ul1 = __shfl_sync(0xffffffffu, sc[ks][2], sh);
            float uh1 = __shfl_sync(0xffffffffu, sc[ks][3], sh);
            uint32_t A0 = f2tf((q & 1) ? vh0 : vl0);
            uint32_t A2 = f2tf((q & 1) ? uh0 : ul0);
            uint32_t A1 = f2tf((q & 1) ? vh1 : vl1);
            uint32_t A3 = f2tf((q & 1) ? uh1 : ul1);
            #pragma unroll
            for (int nv = 0; nv < 8; nv++) {
                const float* bp = &Vt[(nv * 8 + g) * APAD + ks * 8 + q];
                mma_tf32(o[nv], A0, A1, A2, A3,
                         __float_as_uint(bp[0]), __float_as_uint(bp[4]));
            }
        }
        __syncthreads();
    }

    float inv0 = 1.0f / l_r[0];
    float inv1 = 1.0f / l_r[1];
    int r0 = q0 + row0 + g;
    int r1 = r0 + 8;
    #pragma unroll
    for (int nv = 0; nv < 8; nv++) {
        int col = h * DHEAD + nv * 8 + 2 * q;
        float2 w0, w1;
        w0.x = o[nv][0] * inv0; w0.y = o[nv][1] * inv0;
        w1.x = o[nv][2] * inv1; w1.y = o[nv][3] * inv1;
        *(float2*)(O + (size_t)(b*SEQ + r0) * DMODEL + col) = w0;
        *(float2*)(O + (size_t)(b*SEQ + r1) * DMODEL + col) = w1;
    }
}

// =======================================================================
// launch
// =======================================================================
extern "C" void kernel_launch(void* const* d_in, const int* in_sizes, int n_in,
                              void* d_out, int out_size)
{
    const float* x     = (const float*)d_in[0];
    const int*   mask  = (const int*)  d_in[1];
    const float* wq    = (const float*)d_in[2];
    const float* bq    = (const float*)d_in[3];
    const float* wk    = (const float*)d_in[4];
    const float* bk    = (const float*)d_in[5];
    const float* wv    = (const float*)d_in[6];
    const float* bv    = (const float*)d_in[7];
    const float* wo    = (const float*)d_in[8];
    const float* bo    = (const float*)d_in[9];
    const float* ln1_g = (const float*)d_in[10];
    const float* ln1_b = (const float*)d_in[11];
    const float* ln2_g = (const float*)d_in[12];
    const float* ln2_b = (const float*)d_in[13];
    const float* w1    = (const float*)d_in[14];
    const float* b1    = (const float*)d_in[15];
    const float* w2    = (const float*)d_in[16];
    const float* b2    = (const float*)d_in[17];
    float* out = (float*)d_out;

    float *H, *QKV, *CTX, *X2, *FF, *Bqkv;
    __half *Wqkv, *Wo, *W1, *W2;
    cudaGetSymbolAddress((void**)&H,    g_H);
    cudaGetSymbolAddress((void**)&QKV,  g_QKV);
    cudaGetSymbolAddress((void**)&CTX,  g_CTX);
    cudaGetSymbolAddress((void**)&X2,   g_X2);
    cudaGetSymbolAddress((void**)&FF,   g_FF);
    cudaGetSymbolAddress((void**)&Wqkv, g_Wqkv);
    cudaGetSymbolAddress((void**)&Wo,   g_Wo);
    cudaGetSymbolAddress((void**)&W1,   g_W1);
    cudaGetSymbolAddress((void**)&W2,   g_W2);
    cudaGetSymbolAddress((void**)&Bqkv, g_Bqkv);

    cudaFuncSetAttribute(gemm_mma, cudaFuncAttributeMaxDynamicSharedMemorySize, GEMM_SMEM);
    cudaFuncSetAttribute(attn_mma, cudaFuncAttributeMaxDynamicSharedMemorySize, ATTN_SMEM);

    dim3 tb(32, 8);
    transpose_half<<<dim3(DMODEL/32, DMODEL/32), tb>>>(wq, Wqkv,                   DMODEL, DMODEL);
    transpose_half<<<dim3(DMODEL/32, DMODEL/32), tb>>>(wk, Wqkv + DMODEL*DMODEL,   DMODEL, DMODEL);
    transpose_half<<<dim3(DMODEL/32, DMODEL/32), tb>>>(wv, Wqkv + 2*DMODEL*DMODEL, DMODEL, DMODEL);
    transpose_half<<<dim3(DMODEL/32, DMODEL/32), tb>>>(wo, Wo, DMODEL, DMODEL);
    transpose_half<<<dim3(FFDIM/32,  DMODEL/32), tb>>>(w1, W1, DMODEL, FFDIM);
    transpose_half<<<dim3(DMODEL/32, FFDIM/32),  tb>>>(w2, W2, FFDIM, DMODEL);
    concat_bias<<<QKVN/256, 256>>>(bq, bk, bv, Bqkv);

    // residual 1: pre-LN attention
    ln_kernel<<<MTOK, 256>>>(x, ln1_g, ln1_b, H);
    gemm_mma<<<dim3(QKVN/BN, MTOK/BM), 256, GEMM_SMEM>>>(H, Wqkv, Bqkv, nullptr, QKV,
                                                         MTOK, QKVN, DMODEL, 0);
    attn_mma<<<dim3(SEQ/128, NHEADS, BATCH), 256, ATTN_SMEM>>>(QKV, mask, CTX);
    gemm_mma<<<dim3(DMODEL/BN, MTOK/BM), 256, GEMM_SMEM>>>(CTX, Wo, bo, x, X2,
                                                           MTOK, DMODEL, DMODEL, 0);

    // residual 2: pre-LN feed-forward
    ln_kernel<<<MTOK, 256>>>(X2, ln2_g, ln2_b, H);
    gemm_mma<<<dim3(FFDIM/BN, MTOK/BM), 256, GEMM_SMEM>>>(H, W1, b1, nullptr, FF,
                                                          MTOK, FFDIM, DMODEL, 1);
    gemm_mma<<<dim3(DMODEL/BN, MTOK/BM), 256, GEMM_SMEM>>>(FF, W2, b2, X2, out,
                                                           MTOK, DMODEL, FFDIM, 0);
}

// round 13
// speedup vs baseline: 1.4862x; 1.1197x over previous
#include <cuda_runtime.h>
#include <cuda_bf16.h>
#include <cuda_fp16.h>
#include <math.h>
#include <stdint.h>

// ---------------- problem constants ----------------
#define BATCH   2
#define SEQ     2048
#define DMODEL  1024
#define NHEADS  16
#define DHEAD   64
#define FFDIM   4096
#define MTOK    (BATCH * SEQ)          // 4096 token rows
#define QKVN    (3 * DMODEL)           // 3072
#define QKVSTR  3072

// ---------------- scratch (device globals; no allocation) ----------------
__device__ float g_H   [MTOK * DMODEL];
__device__ float g_QKV [MTOK * QKVN];
__device__ float g_CTX [MTOK * DMODEL];
__device__ float g_X2  [MTOK * DMODEL];
__device__ float g_FF  [MTOK * FFDIM];
// fp16 weights, transposed to [N][K] K-major
__device__ __half g_Wqkv[QKVN  * DMODEL];
__device__ __half g_Wo  [DMODEL * DMODEL];
__device__ __half g_W1  [FFDIM * DMODEL];
__device__ __half g_W2  [DMODEL * FFDIM];
__device__ float g_Bqkv[QKVN];

__device__ __forceinline__ uint32_t s2u(const void* p) {
    uint32_t a;
    asm("{ .reg .u64 t; cvta.to.shared.u64 t, %1; cvt.u32.u64 %0, t; }" : "=r"(a) : "l"(p));
    return a;
}
// pack two fp32 -> f16x2 {lo in lower half}
__device__ __forceinline__ uint32_t f16x2(float lo, float hi) {
    uint32_t r; asm("cvt.rn.f16x2.f32 %0, %1, %2;" : "=r"(r) : "f"(hi), "f"(lo)); return r;
}
__device__ __forceinline__ void cp16(uint32_t dst, const void* src) {
    asm volatile("cp.async.cg.shared.global [%0], [%1], 16;" :: "r"(dst), "l"(src));
}
#define CP_COMMIT() asm volatile("cp.async.commit_group;" ::: "memory")
#define CP_WAIT(n)  asm volatile("cp.async.wait_group %0;" :: "n"(n) : "memory")

__device__ __forceinline__ void mma_f16(float c[4], uint32_t a0, uint32_t a1,
                                        uint32_t a2, uint32_t a3,
                                        uint32_t b0, uint32_t b1)
{
    asm volatile(
        "mma.sync.aligned.m16n8k16.row.col.f32.f16.f16.f32 "
        "{%0,%1,%2,%3}, {%4,%5,%6,%7}, {%8,%9}, {%0,%1,%2,%3};"
        : "+f"(c[0]), "+f"(c[1]), "+f"(c[2]), "+f"(c[3])
        : "r"(a0), "r"(a1), "r"(a2), "r"(a3), "r"(b0), "r"(b1));
}

// =======================================================================
// weight transpose + fp16 convert (round-12 version)
// =======================================================================
__global__ void transpose_half(const float* __restrict__ in, __half* __restrict__ out,
                               int K, int N)
{
    __shared__ float tile[32][33];
    int n0 = blockIdx.x * 32, k0 = blockIdx.y * 32;
    int tx = threadIdx.x, ty = threadIdx.y;
    #pragma unroll
    for (int j = 0; j < 32; j += 8)
        tile[ty + j][tx] = in[(size_t)(k0 + ty + j) * N + n0 + tx];
    __syncthreads();
    #pragma unroll
    for (int j = 0; j < 32; j += 8)
        out[(size_t)(n0 + ty + j) * K + k0 + tx] = __float2half_rn(tile[tx][ty + j]);
}

__global__ void concat_bias(const float* __restrict__ a, const float* __restrict__ b,
                            const float* __restrict__ c, float* __restrict__ o)
{
    int i = blockIdx.x * blockDim.x + threadIdx.x;
    if (i < QKVN)
        o[i] = (i < DMODEL) ? a[i] : (i < 2 * DMODEL ? b[i - DMODEL] : c[i - 2 * DMODEL]);
}

// =======================================================================
// LayerNorm (unchanged)
// =======================================================================
__global__ void ln_kernel(const float* __restrict__ x,
                          const float* __restrict__ gamma,
                          const float* __restrict__ beta,
                          float* __restrict__ out)
{
    int row = blockIdx.x;
    int tid = threadIdx.x;
    const float* xr = x + (size_t)row * DMODEL;

    float4 v = *(const float4*)(xr + tid * 4);
    float s  = v.x + v.y + v.z + v.w;
    float sq = v.x*v.x + v.y*v.y + v.z*v.z + v.w*v.w;
    #pragma unroll
    for (int off = 16; off > 0; off >>= 1) {
        s  += __shfl_xor_sync(0xffffffffu, s,  off);
        sq += __shfl_xor_sync(0xffffffffu, sq, off);
    }
    __shared__ float ssum[8], ssq[8];
    int wid = tid >> 5, lane = tid & 31;
    if (lane == 0) { ssum[wid] = s; ssq[wid] = sq; }
    __syncthreads();
    float tot = 0.f, totq = 0.f;
    #pragma unroll
    for (int w = 0; w < 8; w++) { tot += ssum[w]; totq += ssq[w]; }

    const float invN = 1.0f / (float)DMODEL;
    float mean = tot * invN;
    float var  = totq * invN - mean * mean;
    float inv  = rsqrtf(var + 1e-5f);

    float4 g4 = *(const float4*)(gamma + tid * 4);
    float4 b4 = *(const float4*)(beta  + tid * 4);
    float4 o;
    o.x = (v.x - mean) * inv * g4.x + b4.x;
    o.y = (v.y - mean) * inv * g4.y + b4.y;
    o.z = (v.z - mean) * inv * g4.z + b4.z;
    o.w = (v.w - mean) * inv * g4.w + b4.w;
    *(float4*)(out + (size_t)row * DMODEL + tid * 4) = o;
}

// =======================================================================
// fp16 mma.sync GEMM (identical to round 12 — passing, ~200 TF/s)
// =======================================================================
#define BM 128
#define BN 256
#define BK 32
#define PAD_A 40
#define PAD_B 40
#define A_STG_BYTES (128 * PAD_A * 4)       // 20480
#define B_STG_BYTES (256 * PAD_B * 2)       // 20480
#define STG_BYTES   (A_STG_BYTES + B_STG_BYTES)  // 40960
#define NSTAGE 4
#define GEMM_SMEM (NSTAGE * STG_BYTES)      // 163840 B

__global__ __launch_bounds__(256, 1)
void gemm_mma(const float* __restrict__ A, const __half* __restrict__ Wt,
              const float* __restrict__ bias, const float* __restrict__ resid,
              float* __restrict__ C, int M, int N, int K, int relu)
{
    extern __shared__ char smem_raw[];

    int tid  = threadIdx.x;
    int warp = tid >> 5, lane = tid & 31;
    int wm = warp >> 2;
    int wn = warp & 3;
    int g  = lane >> 2;
    int q  = lane & 3;
    int bm = blockIdx.y * BM;
    int bn = blockIdx.x * BN;

    int s_rowA = tid >> 3;
    int s_kqA  = (tid & 7) * 4;
    int s_rowB = tid >> 2;
    int s_kqB  = (tid & 3) * 8;

    const int KT = K / BK;

    auto stage = [&](int st, int kt) {
        uint32_t aBase = s2u(smem_raw + st * STG_BYTES);
        uint32_t bBase = aBase + A_STG_BYTES;
        const float*  ag = A  + (size_t)(bm + s_rowA) * K + kt * BK + s_kqA;
        const __half* bg = Wt + (size_t)(bn + s_rowB) * K + kt * BK + s_kqB;
        #pragma unroll
        for (int i = 0; i < 4; i++)
            cp16(aBase + ((s_rowA + i * 32) * PAD_A + s_kqA) * 4, ag + (size_t)(i * 32) * K);
        #pragma unroll
        for (int i = 0; i < 4; i++)
            cp16(bBase + ((s_rowB + i * 64) * PAD_B + s_kqB) * 2, bg + (size_t)(i * 64) * K);
    };

    float c[4][8][4];
    #pragma unroll
    for (int mi = 0; mi < 4; mi++)
        #pragma unroll
        for (int ni = 0; ni < 8; ni++)
            #pragma unroll
            for (int r = 0; r < 4; r++) c[mi][ni][r] = 0.f;

    stage(0, 0); CP_COMMIT();
    stage(1, 1); CP_COMMIT();
    stage(2, 2); CP_COMMIT();

    for (int kt = 0; kt < KT; kt++) {
        CP_WAIT(2);
        __syncthreads();

        if (kt + 3 < KT) stage((kt + 3) & 3, kt + 3);
        CP_COMMIT();

        const float*  Af = (const float*)(smem_raw + (kt & 3) * STG_BYTES)
                         + (wm * 64 + g) * PAD_A + 2 * q;
        const __half* Bf = (const __half*)(smem_raw + (kt & 3) * STG_BYTES + A_STG_BYTES)
                         + (wn * 64 + g) * PAD_B + 2 * q;

        #pragma unroll
        for (int ks = 0; ks < 2; ks++) {
            uint32_t a[4][4], b[8][2];
            #pragma unroll
            for (int mi = 0; mi < 4; mi++) {
                const float* p = Af + mi * 16 * PAD_A + ks * 16;
                float2 f0 = *(const float2*)(p);
                float2 f1 = *(const float2*)(p + 8 * PAD_A);
                float2 f2 = *(const float2*)(p + 8);
                float2 f3 = *(const float2*)(p + 8 * PAD_A + 8);
                a[mi][0] = f16x2(f0.x, f0.y);
                a[mi][1] = f16x2(f1.x, f1.y);
                a[mi][2] = f16x2(f2.x, f2.y);
                a[mi][3] = f16x2(f3.x, f3.y);
            }
            #pragma unroll
            for (int ni = 0; ni < 8; ni++) {
                const __half* p = Bf + ni * 8 * PAD_B + ks * 16;
                b[ni][0] = *(const uint32_t*)(p);
                b[ni][1] = *(const uint32_t*)(p + 8);
            }
            #pragma unroll
            for (int mi = 0; mi < 4; mi++)
                #pragma unroll
                for (int ni = 0; ni < 8; ni++)
                    mma_f16(c[mi][ni], a[mi][0], a[mi][1], a[mi][2], a[mi][3],
                            b[ni][0], b[ni][1]);
        }
    }

    #pragma unroll
    for (int ni = 0; ni < 8; ni++) {
        int col = bn + wn * 64 + ni * 8 + q * 2;
        float2 bv = *(const float2*)(bias + col);
        #pragma unroll
        for (int mi = 0; mi < 4; mi++) {
            int row = bm + wm * 64 + mi * 16 + g;
            #pragma unroll
            for (int half = 0; half < 2; half++) {
                int r = row + half * 8;
                float2 o;
                o.x = c[mi][ni][half * 2 + 0] + bv.x;
                o.y = c[mi][ni][half * 2 + 1] + bv.y;
                if (resid) {
                    float2 rv = *(const float2*)(resid + (size_t)r * N + col);
                    o.x += rv.x; o.y += rv.y;
                }
                if (relu) { o.x = fmaxf(o.x, 0.f); o.y = fmaxf(o.y, 0.f); }
                *(float2*)(C + (size_t)r * N + col) = o;
            }
        }
    }
}

// =======================================================================
// fp16 tensor-core flash attention (m16n8k16)
// block = 128 q-rows x one (b,h); 8 warps x 16 rows; key tiles of 64.
// Qs fp16 [128][72] (scale folded), Ks fp16 [64][72], Vt fp16 [64 d][72 keys].
// PV A-frags come straight from QK C-frags (f16x2 pack, zero shuffles).
// =======================================================================
#define PQ 72
#define NEG_BIG (-1e30f)
#define ATTN_SMEM ((128 + 64 + 64) * PQ * 2 + 64 * 4)

__global__ __launch_bounds__(256, 1)
void attn_mma(const float* __restrict__ QKV, const int* __restrict__ mask,
              float* __restrict__ O)
{
    extern __shared__ char asm_raw[];
    __half* Qs = (__half*)asm_raw;             // [128][PQ]
    __half* Ks = Qs + 128 * PQ;                // [64][PQ]
    __half* Vt = Ks + 64 * PQ;                 // [64][PQ] (d-major, key minor)
    int*   msk = (int*)(Vt + 64 * PQ);         // [64]

    int tid  = threadIdx.x;
    int warp = tid >> 5, lane = tid & 31;
    int g = lane >> 2, q = lane & 3;
    int row0 = warp * 16;
    int q0 = blockIdx.x * 128;
    int h  = blockIdx.y;
    int b  = blockIdx.z;

    // ---- stage Q (scale 0.125 exact, fp16) ----
    {
        int r  = tid >> 1;
        int c0 = (tid & 1) * 32;
        const float* qp = QKV + (size_t)(b*SEQ + q0 + r) * QKVSTR + h*DHEAD + c0;
        uint32_t* qd = (uint32_t*)&Qs[r * PQ + c0];
        #pragma unroll
        for (int i = 0; i < 8; i++) {
            float4 v = *(const float4*)(qp + i * 4);
            qd[i*2+0] = f16x2(v.x * 0.125f, v.y * 0.125f);
            qd[i*2+1] = f16x2(v.z * 0.125f, v.w * 0.125f);
        }
    }

    float m_r[2] = {NEG_BIG, NEG_BIG};
    float l_r[2] = {0.f, 0.f};
    float o[8][4];
    #pragma unroll
    for (int nv = 0; nv < 8; nv++)
        #pragma unroll
        for (int r = 0; r < 4; r++) o[nv][r] = 0.f;

    for (int t0 = 0; t0 < SEQ; t0 += 64) {
        // ---- stage K fp16 (LDG + cvt + STS.32) ----
        {
            int key = tid >> 2;
            int cb  = (tid & 3) * 16;
            const float* kp = QKV + (size_t)(b*SEQ + t0 + key) * QKVSTR + DMODEL + h*DHEAD + cb;
            uint32_t* kd = (uint32_t*)&Ks[key * PQ + cb];
            #pragma unroll
            for (int i = 0; i < 4; i++) {
                float4 v = *(const float4*)(kp + i * 4);
                kd[i*2+0] = f16x2(v.x, v.y);
                kd[i*2+1] = f16x2(v.z, v.w);
            }
        }
        // ---- stage V transposed fp16 ----
        {
            int key = tid >> 2;
            int db  = (tid & 3) * 16;
            const float* vp = QKV + (size_t)(b*SEQ + t0 + key) * QKVSTR + 2*DMODEL + h*DHEAD + db;
            #pragma unroll
            for (int i = 0; i < 4; i++) {
                float4 v = *(const float4*)(vp + i * 4);
                Vt[(db + i*4 + 0) * PQ + key] = __float2half_rn(v.x);
                Vt[(db + i*4 + 1) * PQ + key] = __float2half_rn(v.y);
                Vt[(db + i*4 + 2) * PQ + key] = __float2half_rn(v.z);
                Vt[(db + i*4 + 3) * PQ + key] = __float2half_rn(v.w);
            }
        }
        if (tid < 64) msk[tid] = mask[b*SEQ + t0 + tid];
        __syncthreads();

        // ---- S = Q @ K^T : 4 k16 steps x 8 col-blocks ----
        float sc[8][4];
        #pragma unroll
        for (int nj = 0; nj < 8; nj++)
            #pragma unroll
            for (int r = 0; r < 4; r++) sc[nj][r] = 0.f;

        const __half* Aq = Qs + (row0 + g) * PQ + 2 * q;
        #pragma unroll
        for (int ks = 0; ks < 4; ks++) {
            const __half* p = Aq + ks * 16;
            uint32_t a0 = *(const uint32_t*)(p);
            uint32_t a1 = *(const uint32_t*)(p + 8 * PQ);
            uint32_t a2 = *(const uint32_t*)(p + 8);
            uint32_t a3 = *(const uint32_t*)(p + 8 * PQ + 8);
            #pragma unroll
            for (int nj = 0; nj < 8; nj++) {
                const __half* bp = Ks + (nj * 8 + g) * PQ + ks * 16 + 2 * q;
                mma_f16(sc[nj], a0, a1, a2, a3,
                        *(const uint32_t*)(bp), *(const uint32_t*)(bp + 8));
            }
        }

        // ---- mask ----
        #pragma unroll
        for (int nj = 0; nj < 8; nj++) {
            int c0 = nj * 8 + 2 * q;
            if (msk[c0]     == 0) { sc[nj][0] = NEG_BIG; sc[nj][2] = NEG_BIG; }
            if (msk[c0 + 1] == 0) { sc[nj][1] = NEG_BIG; sc[nj][3] = NEG_BIG; }
        }

        // ---- online softmax (fp32) ----
        float mx0 = NEG_BIG, mx1 = NEG_BIG;
        #pragma unroll
        for (int nj = 0; nj < 8; nj++) {
            mx0 = fmaxf(mx0, fmaxf(sc[nj][0], sc[nj][1]));
            mx1 = fmaxf(mx1, fmaxf(sc[nj][2], sc[nj][3]));
        }
        mx0 = fmaxf(mx0, __shfl_xor_sync(0xffffffffu, mx0, 1));
        mx0 = fmaxf(mx0, __shfl_xor_sync(0xffffffffu, mx0, 2));
        mx1 = fmaxf(mx1, __shfl_xor_sync(0xffffffffu, mx1, 1));
        mx1 = fmaxf(mx1, __shfl_xor_sync(0xffffffffu, mx1, 2));
        float mn0 = fmaxf(m_r[0], mx0);
        float mn1 = fmaxf(m_r[1], mx1);
        float fac0 = __expf(m_r[0] - mn0);
        float fac1 = __expf(m_r[1] - mn1);

        float sum0 = 0.f, sum1 = 0.f;
        #pragma unroll
        for (int nj = 0; nj < 8; nj++) {
            sc[nj][0] = __expf(sc[nj][0] - mn0);
            sc[nj][1] = __expf(sc[nj][1] - mn0);
            sc[nj][2] = __expf(sc[nj][2] - mn1);
            sc[nj][3] = __expf(sc[nj][3] - mn1);
            sum0 += sc[nj][0] + sc[nj][1];
            sum1 += sc[nj][2] + sc[nj][3];
        }
        sum0 += __shfl_xor_sync(0xffffffffu, sum0, 1);
        sum0 += __shfl_xor_sync(0xffffffffu, sum0, 2);
        sum1 += __shfl_xor_sync(0xffffffffu, sum1, 1);
        sum1 += __shfl_xor_sync(0xffffffffu, sum1, 2);

        l_r[0] = l_r[0] * fac0 + sum0;  m_r[0] = mn0;
        l_r[1] = l_r[1] * fac1 + sum1;  m_r[1] = mn1;

        #pragma unroll
        for (int nv = 0; nv < 8; nv++) {
            o[nv][0] *= fac0; o[nv][1] *= fac0;
            o[nv][2] *= fac1; o[nv][3] *= fac1;
        }

        // ---- O += P @ V : A-frags direct from C-frags (no shuffles) ----
        #pragma unroll
        for (int ks = 0; ks < 4; ks++) {
            uint32_t A0 = f16x2(sc[2*ks][0],   sc[2*ks][1]);    // row g,   keys 16ks+2q,+1
            uint32_t A1 = f16x2(sc[2*ks][2],   sc[2*ks][3]);    // row g+8
            uint32_t A2 = f16x2(sc[2*ks+1][0], sc[2*ks+1][1]);  // row g,   keys +8
            uint32_t A3 = f16x2(sc[2*ks+1][2], sc[2*ks+1][3]);  // row g+8, keys +8
            #pragma unroll
            for (int nv = 0; nv < 8; nv++) {
                const __half* bp = Vt + (nv * 8 + g) * PQ + ks * 16 + 2 * q;
                mma_f16(o[nv], A0, A1, A2, A3,
                        *(const uint32_t*)(bp), *(const uint32_t*)(bp + 8));
            }
        }
        __syncthreads();
    }

    // ---- write ctx ----
    float inv0 = 1.0f / l_r[0];
    float inv1 = 1.0f / l_r[1];
    int r0 = q0 + row0 + g;
    int r1 = r0 + 8;
    #pragma unroll
    for (int nv = 0; nv < 8; nv++) {
        int col = h * DHEAD + nv * 8 + 2 * q;
        float2 w0, w1;
        w0.x = o[nv][0] * inv0; w0.y = o[nv][1] * inv0;
        w1.x = o[nv][2] * inv1; w1.y = o[nv][3] * inv1;
        *(float2*)(O + (size_t)(b*SEQ + r0) * DMODEL + col) = w0;
        *(float2*)(O + (size_t)(b*SEQ + r1) * DMODEL + col) = w1;
    }
}

// =======================================================================
// launch
// =======================================================================
extern "C" void kernel_launch(void* const* d_in, const int* in_sizes, int n_in,
                              void* d_out, int out_size)
{
    const float* x     = (const float*)d_in[0];
    const int*   mask  = (const int*)  d_in[1];
    const float* wq    = (const float*)d_in[2];
    const float* bq    = (const float*)d_in[3];
    const float* wk    = (const float*)d_in[4];
    const float* bk    = (const float*)d_in[5];
    const float* wv    = (const float*)d_in[6];
    const float* bv    = (const float*)d_in[7];
    const float* wo    = (const float*)d_in[8];
    const float* bo    = (const float*)d_in[9];
    const float* ln1_g = (const float*)d_in[10];
    const float* ln1_b = (const float*)d_in[11];
    const float* ln2_g = (const float*)d_in[12];
    const float* ln2_b = (const float*)d_in[13];
    const float* w1    = (const float*)d_in[14];
    const float* b1    = (const float*)d_in[15];
    const float* w2    = (const float*)d_in[16];
    const float* b2    = (const float*)d_in[17];
    float* out = (float*)d_out;

    float *H, *QKV, *CTX, *X2, *FF, *Bqkv;
    __half *Wqkv, *Wo, *W1, *W2;
    cudaGetSymbolAddress((void**)&H,    g_H);
    cudaGetSymbolAddress((void**)&QKV,  g_QKV);
    cudaGetSymbolAddress((void**)&CTX,  g_CTX);
    cudaGetSymbolAddress((void**)&X2,   g_X2);
    cudaGetSymbolAddress((void**)&FF,   g_FF);
    cudaGetSymbolAddress((void**)&Wqkv, g_Wqkv);
    cudaGetSymbolAddress((void**)&Wo,   g_Wo);
    cudaGetSymbolAddress((void**)&W1,   g_W1);
    cudaGetSymbolAddress((void**)&W2,   g_W2);
    cudaGetSymbolAddress((void**)&Bqkv, g_Bqkv);

    cudaFuncSetAttribute(gemm_mma, cudaFuncAttributeMaxDynamicSharedMemorySize, GEMM_SMEM);
    cudaFuncSetAttribute(attn_mma, cudaFuncAttributeMaxDynamicSharedMemorySize, ATTN_SMEM);

    dim3 tb(32, 8);
    transpose_half<<<dim3(DMODEL/32, DMODEL/32), tb>>>(wq, Wqkv,                   DMODEL, DMODEL);
    transpose_half<<<dim3(DMODEL/32, DMODEL/32), tb>>>(wk, Wqkv + DMODEL*DMODEL,   DMODEL, DMODEL);
    transpose_half<<<dim3(DMODEL/32, DMODEL/32), tb>>>(wv, Wqkv + 2*DMODEL*DMODEL, DMODEL, DMODEL);
    transpose_half<<<dim3(DMODEL/32, DMODEL/32), tb>>>(wo, Wo, DMODEL, DMODEL);
    transpose_half<<<dim3(FFDIM/32,  DMODEL/32), tb>>>(w1, W1, DMODEL, FFDIM);
    transpose_half<<<dim3(DMODEL/32, FFDIM/32),  tb>>>(w2, W2, FFDIM, DMODEL);
    concat_bias<<<QKVN/256, 256>>>(bq, bk, bv, Bqkv);

    // residual 1: pre-LN attention
    ln_kernel<<<MTOK, 256>>>(x, ln1_g, ln1_b, H);
    gemm_mma<<<dim3(QKVN/BN, MTOK/BM), 256, GEMM_SMEM>>>(H, Wqkv, Bqkv, nullptr, QKV,
                                                         MTOK, QKVN, DMODEL, 0);
    attn_mma<<<dim3(SEQ/128, NHEADS, BATCH), 256, ATTN_SMEM>>>(QKV, mask, CTX);
    gemm_mma<<<dim3(DMODEL/BN, MTOK/BM), 256, GEMM_SMEM>>>(CTX, Wo, bo, x, X2,
                                                           MTOK, DMODEL, DMODEL, 0);

    // residual 2: pre-LN feed-forward
    ln_kernel<<<MTOK, 256>>>(X2, ln2_g, ln2_b, H);
    gemm_mma<<<dim3(FFDIM/BN, MTOK/BM), 256, GEMM_SMEM>>>(H, W1, b1, nullptr, FF,
                                                          MTOK, FFDIM, DMODEL, 1);
    gemm_mma<<<dim3(DMODEL/BN, MTOK/BM), 256, GEMM_SMEM>>>(FF, W2, b2, X2, out,
                                                           MTOK, DMODEL, FFDIM, 0);
}

// round 15
// speedup vs baseline: 1.6328x; 1.0987x over previous
#include <cuda_runtime.h>
#include <cuda_bf16.h>
#include <cuda_fp16.h>
#include <math.h>
#include <stdint.h>

// ---------------- problem constants ----------------
#define BATCH   2
#define SEQ     2048
#define DMODEL  1024
#define NHEADS  16
#define DHEAD   64
#define FFDIM   4096
#define MTOK    (BATCH * SEQ)          // 4096 token rows
#define QKVN    (3 * DMODEL)           // 3072
#define QKVSTR  3072

// ---------------- scratch (device globals; no allocation) ----------------
__device__ __half g_H   [MTOK * DMODEL];   // LN output (fp16)
__device__ __half g_QKV [MTOK * QKVN];     // fused qkv (fp16, q pre-scaled by 1/8)
__device__ __half g_CTX [MTOK * DMODEL];   // attention output (fp16)
__device__ float  g_X2  [MTOK * DMODEL];   // residual-1 output (fp32)
__device__ __half g_FF  [MTOK * FFDIM];    // FF hidden (fp16)
__device__ __half g_Wqkv[QKVN  * DMODEL];  // [N][K], wq rows pre-scaled by 1/8
__device__ __half g_Wo  [DMODEL * DMODEL];
__device__ __half g_W1  [FFDIM * DMODEL];
__device__ __half g_W2  [DMODEL * FFDIM];
__device__ float  g_Bqkv[QKVN];            // bq pre-scaled by 1/8

__device__ __forceinline__ uint32_t s2u(const void* p) {
    uint32_t a;
    asm("{ .reg .u64 t; cvta.to.shared.u64 t, %1; cvt.u32.u64 %0, t; }" : "=r"(a) : "l"(p));
    return a;
}
__device__ __forceinline__ uint32_t f16x2(float lo, float hi) {
    uint32_t r; asm("cvt.rn.f16x2.f32 %0, %1, %2;" : "=r"(r) : "f"(hi), "f"(lo)); return r;
}
__device__ __forceinline__ void cp16(uint32_t dst, const void* src) {
    asm volatile("cp.async.cg.shared.global [%0], [%1], 16;" :: "r"(dst), "l"(src));
}
#define CP_COMMIT() asm volatile("cp.async.commit_group;" ::: "memory")
#define CP_WAIT(n)  asm volatile("cp.async.wait_group %0;" :: "n"(n) : "memory")

__device__ __forceinline__ void mma_f16(float c[4], uint32_t a0, uint32_t a1,
                                        uint32_t a2, uint32_t a3,
                                        uint32_t b0, uint32_t b1)
{
    asm volatile(
        "mma.sync.aligned.m16n8k16.row.col.f32.f16.f16.f32 "
        "{%0,%1,%2,%3}, {%4,%5,%6,%7}, {%8,%9}, {%0,%1,%2,%3};"
        : "+f"(c[0]), "+f"(c[1]), "+f"(c[2]), "+f"(c[3])
        : "r"(a0), "r"(a1), "r"(a2), "r"(a3), "r"(b0), "r"(b1));
}

// =======================================================================
// weight transpose + fp16 convert (+scale): out[n][k] = f16(in[k][n]*s)
// scale=0.125 for wq is exact (power of 2) -> identical math to scaling Q.
// =======================================================================
__global__ void transpose_half(const float* __restrict__ in, __half* __restrict__ out,
                               int K, int N, float scale)
{
    __shared__ float tile[32][33];
    int n0 = blockIdx.x * 32, k0 = blockIdx.y * 32;
    int tx = threadIdx.x, ty = threadIdx.y;
    #pragma unroll
    for (int j = 0; j < 32; j += 8)
        tile[ty + j][tx] = in[(size_t)(k0 + ty + j) * N + n0 + tx];
    __syncthreads();
    #pragma unroll
    for (int j = 0; j < 32; j += 8)
        out[(size_t)(n0 + ty + j) * K + k0 + tx] = __float2half_rn(tile[tx][ty + j] * scale);
}

__global__ void concat_bias(const float* __restrict__ a, const float* __restrict__ b,
                            const float* __restrict__ c, float* __restrict__ o)
{
    int i = blockIdx.x * blockDim.x + threadIdx.x;
    if (i < QKVN)
        o[i] = (i < DMODEL) ? a[i] * 0.125f
             : (i < 2 * DMODEL ? b[i - DMODEL] : c[i - 2 * DMODEL]);
}

// =======================================================================
// LayerNorm: fp32 in -> fp16 out
// =======================================================================
__global__ void ln_kernel(const float* __restrict__ x,
                          const float* __restrict__ gamma,
                          const float* __restrict__ beta,
                          __half* __restrict__ out)
{
    int row = blockIdx.x;
    int tid = threadIdx.x;
    const float* xr = x + (size_t)row * DMODEL;

    float4 v = *(const float4*)(xr + tid * 4);
    float s  = v.x + v.y + v.z + v.w;
    float sq = v.x*v.x + v.y*v.y + v.z*v.z + v.w*v.w;
    #pragma unroll
    for (int off = 16; off > 0; off >>= 1) {
        s  += __shfl_xor_sync(0xffffffffu, s,  off);
        sq += __shfl_xor_sync(0xffffffffu, sq, off);
    }
    __shared__ float ssum[8], ssq[8];
    int wid = tid >> 5, lane = tid & 31;
    if (lane == 0) { ssum[wid] = s; ssq[wid] = sq; }
    __syncthreads();
    float tot = 0.f, totq = 0.f;
    #pragma unroll
    for (int w = 0; w < 8; w++) { tot += ssum[w]; totq += ssq[w]; }

    const float invN = 1.0f / (float)DMODEL;
    float mean = tot * invN;
    float var  = totq * invN - mean * mean;
    float inv  = rsqrtf(var + 1e-5f);

    float4 g4 = *(const float4*)(gamma + tid * 4);
    float4 b4 = *(const float4*)(beta  + tid * 4);
    uint32_t* op = (uint32_t*)(out + (size_t)row * DMODEL + tid * 4);
    op[0] = f16x2((v.x - mean) * inv * g4.x + b4.x, (v.y - mean) * inv * g4.y + b4.y);
    op[1] = f16x2((v.z - mean) * inv * g4.z + b4.z, (v.w - mean) * inv * g4.w + b4.w);
}

// =======================================================================
// fp16 mma.sync GEMM: C = A[M,K](fp16) @ Wt[N,K]^T(fp16) + bias
// output: Ch (fp16) if non-null, else Cf (fp32, +resid).  relu on request.
// block 128x256, BK=32; warp tile 64x64; 4-stage single-sync pipeline.
// =======================================================================
#define BM 128
#define BN 256
#define BK 32
#define PAD_A 40
#define PAD_B 40
#define A_STG_BYTES (128 * PAD_A * 2)       // 10240
#define B_STG_BYTES (256 * PAD_B * 2)       // 20480
#define STG_BYTES   (A_STG_BYTES + B_STG_BYTES)  // 30720
#define NSTAGE 4
#define GEMM_SMEM (NSTAGE * STG_BYTES)      // 122880 B

__global__ __launch_bounds__(256, 1)
void gemm_mma(const __half* __restrict__ A, const __half* __restrict__ Wt,
              const float* __restrict__ bias, const float* __restrict__ resid,
              float* __restrict__ Cf, __half* __restrict__ Ch,
              int M, int N, int K, int relu)
{
    extern __shared__ char smem_raw[];

    int tid  = threadIdx.x;
    int warp = tid >> 5, lane = tid & 31;
    int wm = warp >> 2;
    int wn = warp & 3;
    int g  = lane >> 2;
    int q  = lane & 3;
    int bm = blockIdx.y * BM;
    int bn = blockIdx.x * BN;

    // A staging: 128 rows x 64B -> 512 chunks, 2/thread
    int s_rowA = tid >> 2;             // 0..63 (+64)
    int s_kqA  = (tid & 3) * 8;        // halves
    // B staging: 256 rows x 64B -> 1024 chunks, 4/thread
    int s_rowB = tid >> 2;             // 0..63 (+64i)
    int s_kqB  = (tid & 3) * 8;

    const int KT = K / BK;

    auto stage = [&](int st, int kt) {
        uint32_t aBase = s2u(smem_raw + st * STG_BYTES);
        uint32_t bBase = aBase + A_STG_BYTES;
        const __half* ag = A  + (size_t)(bm + s_rowA) * K + kt * BK + s_kqA;
        const __half* bg = Wt + (size_t)(bn + s_rowB) * K + kt * BK + s_kqB;
        #pragma unroll
        for (int i = 0; i < 2; i++)
            cp16(aBase + ((s_rowA + i * 64) * PAD_A + s_kqA) * 2, ag + (size_t)(i * 64) * K);
        #pragma unroll
        for (int i = 0; i < 4; i++)
            cp16(bBase + ((s_rowB + i * 64) * PAD_B + s_kqB) * 2, bg + (size_t)(i * 64) * K);
    };

    float c[4][8][4];
    #pragma unroll
    for (int mi = 0; mi < 4; mi++)
        #pragma unroll
        for (int ni = 0; ni < 8; ni++)
            #pragma unroll
            for (int r = 0; r < 4; r++) c[mi][ni][r] = 0.f;

    stage(0, 0); CP_COMMIT();
    stage(1, 1); CP_COMMIT();
    stage(2, 2); CP_COMMIT();

    for (int kt = 0; kt < KT; kt++) {
        CP_WAIT(2);
        __syncthreads();

        if (kt + 3 < KT) stage((kt + 3) & 3, kt + 3);
        CP_COMMIT();

        const __half* Af = (const __half*)(smem_raw + (kt & 3) * STG_BYTES)
                         + (wm * 64 + g) * PAD_A + 2 * q;
        const __half* Bf = (const __half*)(smem_raw + (kt & 3) * STG_BYTES + A_STG_BYTES)
                         + (wn * 64 + g) * PAD_B + 2 * q;

        #pragma unroll
        for (int ks = 0; ks < 2; ks++) {
            uint32_t a[4][4], b[8][2];
            #pragma unroll
            for (int mi = 0; mi < 4; mi++) {
                const __half* p = Af + mi * 16 * PAD_A + ks * 16;
                a[mi][0] = *(const uint32_t*)(p);
                a[mi][1] = *(const uint32_t*)(p + 8 * PAD_A);
                a[mi][2] = *(const uint32_t*)(p + 8);
                a[mi][3] = *(const uint32_t*)(p + 8 * PAD_A + 8);
            }
            #pragma unroll
            for (int ni = 0; ni < 8; ni++) {
                const __half* p = Bf + ni * 8 * PAD_B + ks * 16;
                b[ni][0] = *(const uint32_t*)(p);
                b[ni][1] = *(const uint32_t*)(p + 8);
            }
            #pragma unroll
            for (int mi = 0; mi < 4; mi++)
                #pragma unroll
                for (int ni = 0; ni < 8; ni++)
                    mma_f16(c[mi][ni], a[mi][0], a[mi][1], a[mi][2], a[mi][3],
                            b[ni][0], b[ni][1]);
        }
    }

    // ---- epilogue ----
    #pragma unroll
    for (int ni = 0; ni < 8; ni++) {
        int col = bn + wn * 64 + ni * 8 + q * 2;
        float2 bv = *(const float2*)(bias + col);
        #pragma unroll
        for (int mi = 0; mi < 4; mi++) {
            int row = bm + wm * 64 + mi * 16 + g;
            #pragma unroll
            for (int half = 0; half < 2; half++) {
                int r = row + half * 8;
                float ox = c[mi][ni][half * 2 + 0] + bv.x;
                float oy = c[mi][ni][half * 2 + 1] + bv.y;
                if (relu) { ox = fmaxf(ox, 0.f); oy = fmaxf(oy, 0.f); }
                if (Ch) {
                    *(uint32_t*)(Ch + (size_t)r * N + col) = f16x2(ox, oy);
                } else {
                    if (resid) {
                        float2 rv = *(const float2*)(resid + (size_t)r * N + col);
                        ox += rv.x; oy += rv.y;
                    }
                    float2 o; o.x = ox; o.y = oy;
                    *(float2*)(Cf + (size_t)r * N + col) = o;
                }
            }
        }
    }
}

// =======================================================================
// fp16 flash attention (m16n8k16); QKV fp16 (q pre-scaled), CTX fp16 out.
// Q/K staged via cp.async; V transposed via LDG(half2)+scalar STS.
// =======================================================================
#define PQ 72
#define NEG_BIG (-1e30f)
#define ATTN_SMEM ((128 + 64 + 64) * PQ * 2 + 64 * 4)

__global__ __launch_bounds__(256, 1)
void attn_mma(const __half* __restrict__ QKV, const int* __restrict__ mask,
              __half* __restrict__ O)
{
    extern __shared__ char asm_raw[];
    __half* Qs = (__half*)asm_raw;             // [128][PQ]
    __half* Ks = Qs + 128 * PQ;                // [64][PQ]
    __half* Vt = Ks + 64 * PQ;                 // [64][PQ] (d-major, key minor)
    int*   msk = (int*)(Vt + 64 * PQ);         // [64]

    int tid  = threadIdx.x;
    int warp = tid >> 5, lane = tid & 31;
    int g = lane >> 2, q = lane & 3;
    int row0 = warp * 16;
    int q0 = blockIdx.x * 128;
    int h  = blockIdx.y;
    int b  = blockIdx.z;

    // ---- stage Q via cp.async: 128 rows x 128B = 1024 chunks, 4/thread ----
    {
        int r  = tid >> 1;                       // 0..127
        int c0 = (tid & 1) * 32;                 // halves
        const __half* qp = QKV + (size_t)(b*SEQ + q0 + r) * QKVSTR + h*DHEAD + c0;
        uint32_t qd = s2u(&Qs[r * PQ + c0]);
        #pragma unroll
        for (int i = 0; i < 4; i++)
            cp16(qd + i * 16, qp + i * 8);
    }

    float m_r[2] = {NEG_BIG, NEG_BIG};
    float l_r[2] = {0.f, 0.f};
    float o[8][4];
    #pragma unroll
    for (int nv = 0; nv < 8; nv++)
        #pragma unroll
        for (int r = 0; r < 4; r++) o[nv][r] = 0.f;

    for (int t0 = 0; t0 < SEQ; t0 += 64) {
        // ---- stage K via cp.async: 64 rows x 128B = 512 chunks, 2/thread ----
        {
            int key = tid >> 2;
            int cb  = (tid & 3) * 8;             // halves
            const __half* kp = QKV + (size_t)(b*SEQ + t0 + key) * QKVSTR + DMODEL + h*DHEAD + cb;
            uint32_t kd = s2u(&Ks[key * PQ + cb]);
            cp16(kd,      kp);
            cp16(kd + 64, kp + 32);
        }
        CP_COMMIT();
        // ---- stage V transposed (fp16 LDG + scalar STS) ----
        {
            int key = tid >> 2;
            int db  = (tid & 3) * 16;
            const __half2* vp = (const __half2*)(QKV + (size_t)(b*SEQ + t0 + key) * QKVSTR
                                                 + 2*DMODEL + h*DHEAD + db);
            #pragma unroll
            for (int i = 0; i < 8; i++) {
                __half2 v = vp[i];
                Vt[(db + 2*i + 0) * PQ + key] = __low2half(v);
                Vt[(db + 2*i + 1) * PQ + key] = __high2half(v);
            }
        }
        if (tid < 64) msk[tid] = mask[b*SEQ + t0 + tid];
        CP_WAIT(0);
        __syncthreads();

        // ---- S = Q @ K^T ----
        float sc[8][4];
        #pragma unroll
        for (int nj = 0; nj < 8; nj++)
            #pragma unroll
            for (int r = 0; r < 4; r++) sc[nj][r] = 0.f;

        const __half* Aq = Qs + (row0 + g) * PQ + 2 * q;
        #pragma unroll
        for (int ks = 0; ks < 4; ks++) {
            const __half* p = Aq + ks * 16;
            uint32_t a0 = *(const uint32_t*)(p);
            uint32_t a1 = *(const uint32_t*)(p + 8 * PQ);
            uint32_t a2 = *(const uint32_t*)(p + 8);
            uint32_t a3 = *(const uint32_t*)(p + 8 * PQ + 8);
            #pragma unroll
            for (int nj = 0; nj < 8; nj++) {
                const __half* bp = Ks + (nj * 8 + g) * PQ + ks * 16 + 2 * q;
                mma_f16(sc[nj], a0, a1, a2, a3,
                        *(const uint32_t*)(bp), *(const uint32_t*)(bp + 8));
            }
        }

        // ---- mask ----
        #pragma unroll
        for (int nj = 0; nj < 8; nj++) {
            int c0 = nj * 8 + 2 * q;
            if (msk[c0]     == 0) { sc[nj][0] = NEG_BIG; sc[nj][2] = NEG_BIG; }
            if (msk[c0 + 1] == 0) { sc[nj][1] = NEG_BIG; sc[nj][3] = NEG_BIG; }
        }

        // ---- online softmax ----
        float mx0 = NEG_BIG, mx1 = NEG_BIG;
        #pragma unroll
        for (int nj = 0; nj < 8; nj++) {
            mx0 = fmaxf(mx0, fmaxf(sc[nj][0], sc[nj][1]));
            mx1 = fmaxf(mx1, fmaxf(sc[nj][2], sc[nj][3]));
        }
        mx0 = fmaxf(mx0, __shfl_xor_sync(0xffffffffu, mx0, 1));
        mx0 = fmaxf(mx0, __shfl_xor_sync(0xffffffffu, mx0, 2));
        mx1 = fmaxf(mx1, __shfl_xor_sync(0xffffffffu, mx1, 1));
        mx1 = fmaxf(mx1, __shfl_xor_sync(0xffffffffu, mx1, 2));
        float mn0 = fmaxf(m_r[0], mx0);
        float mn1 = fmaxf(m_r[1], mx1);
        float fac0 = __expf(m_r[0] - mn0);
        float fac1 = __expf(m_r[1] - mn1);

        float sum0 = 0.f, sum1 = 0.f;
        #pragma unroll
        for (int nj = 0; nj < 8; nj++) {
            sc[nj][0] = __expf(sc[nj][0] - mn0);
            sc[nj][1] = __expf(sc[nj][1] - mn0);
            sc[nj][2] = __expf(sc[nj][2] - mn1);
            sc[nj][3] = __expf(sc[nj][3] - mn1);
            sum0 += sc[nj][0] + sc[nj][1];
            sum1 += sc[nj][2] + sc[nj][3];
        }
        sum0 += __shfl_xor_sync(0xffffffffu, sum0, 1);
        sum0 += __shfl_xor_sync(0xffffffffu, sum0, 2);
        sum1 += __shfl_xor_sync(0xffffffffu, sum1, 1);
        sum1 += __shfl_xor_sync(0xffffffffu, sum1, 2);

        l_r[0] = l_r[0] * fac0 + sum0;  m_r[0] = mn0;
        l_r[1] = l_r[1] * fac1 + sum1;  m_r[1] = mn1;

        #pragma unroll
        for (int nv = 0; nv < 8; nv++) {
            o[nv][0] *= fac0; o[nv][1] *= fac0;
            o[nv][2] *= fac1; o[nv][3] *= fac1;
        }

        // ---- O += P @ V (A-frags direct from C-frags) ----
        #pragma unroll
        for (int ks = 0; ks < 4; ks++) {
            uint32_t A0 = f16x2(sc[2*ks][0],   sc[2*ks][1]);
            uint32_t A1 = f16x2(sc[2*ks][2],   sc[2*ks][3]);
            uint32_t A2 = f16x2(sc[2*ks+1][0], sc[2*ks+1][1]);
            uint32_t A3 = f16x2(sc[2*ks+1][2], sc[2*ks+1][3]);
            #pragma unroll
            for (int nv = 0; nv < 8; nv++) {
                const __half* bp = Vt + (nv * 8 + g) * PQ + ks * 16 + 2 * q;
                mma_f16(o[nv], A0, A1, A2, A3,
                        *(const uint32_t*)(bp), *(const uint32_t*)(bp + 8));
            }
        }
        __syncthreads();
    }

    // ---- write ctx (fp16) ----
    float inv0 = 1.0f / l_r[0];
    float inv1 = 1.0f / l_r[1];
    int r0 = q0 + row0 + g;
    int r1 = r0 + 8;
    #pragma unroll
    for (int nv = 0; nv < 8; nv++) {
        int col = h * DHEAD + nv * 8 + 2 * q;
        *(uint32_t*)(O + (size_t)(b*SEQ + r0) * DMODEL + col) = f16x2(o[nv][0]*inv0, o[nv][1]*inv0);
        *(uint32_t*)(O + (size_t)(b*SEQ + r1) * DMODEL + col) = f16x2(o[nv][2]*inv1, o[nv][3]*inv1);
    }
}

// =======================================================================
// launch
// =======================================================================
extern "C" void kernel_launch(void* const* d_in, const int* in_sizes, int n_in,
                              void* d_out, int out_size)
{
    const float* x     = (const float*)d_in[0];
    const int*   mask  = (const int*)  d_in[1];
    const float* wq    = (const float*)d_in[2];
    const float* bq    = (const float*)d_in[3];
    const float* wk    = (const float*)d_in[4];
    const float* bk    = (const float*)d_in[5];
    const float* wv    = (const float*)d_in[6];
    const float* bv    = (const float*)d_in[7];
    const float* wo    = (const float*)d_in[8];
    const float* bo    = (const float*)d_in[9];
    const float* ln1_g = (const float*)d_in[10];
    const float* ln1_b = (const float*)d_in[11];
    const float* ln2_g = (const float*)d_in[12];
    const float* ln2_b = (const float*)d_in[13];
    const float* w1    = (const float*)d_in[14];
    const float* b1    = (const float*)d_in[15];
    const float* w2    = (const float*)d_in[16];
    const float* b2    = (const float*)d_in[17];
    float* out = (float*)d_out;

    float *X2, *Bqkv;
    __half *H, *QKV, *CTX, *FF, *Wqkv, *Wo, *W1, *W2;
    cudaGetSymbolAddress((void**)&H,    g_H);
    cudaGetSymbolAddress((void**)&QKV,  g_QKV);
    cudaGetSymbolAddress((void**)&CTX,  g_CTX);
    cudaGetSymbolAddress((void**)&X2,   g_X2);
    cudaGetSymbolAddress((void**)&FF,   g_FF);
    cudaGetSymbolAddress((void**)&Wqkv, g_Wqkv);
    cudaGetSymbolAddress((void**)&Wo,   g_Wo);
    cudaGetSymbolAddress((void**)&W1,   g_W1);
    cudaGetSymbolAddress((void**)&W2,   g_W2);
    cudaGetSymbolAddress((void**)&Bqkv, g_Bqkv);

    cudaFuncSetAttribute(gemm_mma, cudaFuncAttributeMaxDynamicSharedMemorySize, GEMM_SMEM);
    cudaFuncSetAttribute(attn_mma, cudaFuncAttributeMaxDynamicSharedMemorySize, ATTN_SMEM);

    dim3 tb(32, 8);
    transpose_half<<<dim3(DMODEL/32, DMODEL/32), tb>>>(wq, Wqkv,                   DMODEL, DMODEL, 0.125f);
    transpose_half<<<dim3(DMODEL/32, DMODEL/32), tb>>>(wk, Wqkv + DMODEL*DMODEL,   DMODEL, DMODEL, 1.0f);
    transpose_half<<<dim3(DMODEL/32, DMODEL/32), tb>>>(wv, Wqkv + 2*DMODEL*DMODEL, DMODEL, DMODEL, 1.0f);
    transpose_half<<<dim3(DMODEL/32, DMODEL/32), tb>>>(wo, Wo, DMODEL, DMODEL, 1.0f);
    transpose_half<<<dim3(FFDIM/32,  DMODEL/32), tb>>>(w1, W1, DMODEL, FFDIM, 1.0f);
    transpose_half<<<dim3(DMODEL/32, FFDIM/32),  tb>>>(w2, W2, FFDIM, DMODEL, 1.0f);
    concat_bias<<<QKVN/256, 256>>>(bq, bk, bv, Bqkv);

    // residual 1: pre-LN attention
    ln_kernel<<<MTOK, 256>>>(x, ln1_g, ln1_b, H);
    gemm_mma<<<dim3(QKVN/BN, MTOK/BM), 256, GEMM_SMEM>>>(H, Wqkv, Bqkv, nullptr,
                                                         nullptr, QKV, MTOK, QKVN, DMODEL, 0);
    attn_mma<<<dim3(SEQ/128, NHEADS, BATCH), 256, ATTN_SMEM>>>(QKV, mask, CTX);
    gemm_mma<<<dim3(DMODEL/BN, MTOK/BM), 256, GEMM_SMEM>>>(CTX, Wo, bo, x,
                                                           X2, nullptr, MTOK, DMODEL, DMODEL, 0);

    // residual 2: pre-LN feed-forward
    ln_kernel<<<MTOK, 256>>>(X2, ln2_g, ln2_b, H);
    gemm_mma<<<dim3(FFDIM/BN, MTOK/BM), 256, GEMM_SMEM>>>(H, W1, b1, nullptr,
                                                          nullptr, FF, MTOK, FFDIM, DMODEL, 1);
    gemm_mma<<<dim3(DMODEL/BN, MTOK/BM), 256, GEMM_SMEM>>>(FF, W2, b2, X2,
                                                           out, nullptr, MTOK, DMODEL, FFDIM, 0);
}

// round 16
// speedup vs baseline: 1.6474x; 1.0089x over previous
#include <cuda_runtime.h>
#include <cuda_bf16.h>
#include <cuda_fp16.h>
#include <math.h>
#include <stdint.h>

// ---------------- problem constants ----------------
#define BATCH   2
#define SEQ     2048
#define DMODEL  1024
#define NHEADS  16
#define DHEAD   64
#define FFDIM   4096
#define MTOK    (BATCH * SEQ)          // 4096 token rows
#define QKVN    (3 * DMODEL)           // 3072
#define QKVSTR  3072

// ---------------- scratch (device globals; no allocation) ----------------
__device__ __half g_H   [MTOK * DMODEL];   // LN output (fp16)
__device__ __half g_QKV [MTOK * QKVN];     // fused qkv (fp16, q pre-scaled by 1/8)
__device__ __half g_CTX [MTOK * DMODEL];   // attention output (fp16)
__device__ float  g_X2  [MTOK * DMODEL];   // residual-1 output (fp32)
__device__ __half g_FF  [MTOK * FFDIM];    // FF hidden (fp16)
__device__ __half g_Wqkv[QKVN  * DMODEL];  // [N][K], wq rows pre-scaled by 1/8
__device__ __half g_Wo  [DMODEL * DMODEL];
__device__ __half g_W1  [FFDIM * DMODEL];
__device__ __half g_W2  [DMODEL * FFDIM];
__device__ float  g_Bqkv[QKVN];            // bq pre-scaled by 1/8

__device__ __forceinline__ uint32_t s2u(const void* p) {
    uint32_t a;
    asm("{ .reg .u64 t; cvta.to.shared.u64 t, %1; cvt.u32.u64 %0, t; }" : "=r"(a) : "l"(p));
    return a;
}
__device__ __forceinline__ uint32_t f16x2(float lo, float hi) {
    uint32_t r; asm("cvt.rn.f16x2.f32 %0, %1, %2;" : "=r"(r) : "f"(hi), "f"(lo)); return r;
}
__device__ __forceinline__ void cp16(uint32_t dst, const void* src) {
    asm volatile("cp.async.cg.shared.global [%0], [%1], 16;" :: "r"(dst), "l"(src));
}
#define CP_COMMIT() asm volatile("cp.async.commit_group;" ::: "memory")
#define CP_WAIT(n)  asm volatile("cp.async.wait_group %0;" :: "n"(n) : "memory")

__device__ __forceinline__ void mma_f16(float c[4], uint32_t a0, uint32_t a1,
                                        uint32_t a2, uint32_t a3,
                                        uint32_t b0, uint32_t b1)
{
    asm volatile(
        "mma.sync.aligned.m16n8k16.row.col.f32.f16.f16.f32 "
        "{%0,%1,%2,%3}, {%4,%5,%6,%7}, {%8,%9}, {%0,%1,%2,%3};"
        : "+f"(c[0]), "+f"(c[1]), "+f"(c[2]), "+f"(c[3])
        : "r"(a0), "r"(a1), "r"(a2), "r"(a3), "r"(b0), "r"(b1));
}

// =======================================================================
// fused weight transpose + fp16 convert (+scale) — ONE launch for all 6.
// out[n][k] = f16(in[k][n]*s).  wq scaled by 1/8 (exact power of 2).
// blocks: [0,4096) = wq,wk,wv,wo (1024x1024); [4096,8192) w1; [8192,12288) w2
// =======================================================================
#define TRN_BLOCKS 12288

__global__ void transpose_all(const float* __restrict__ wq, const float* __restrict__ wk,
                              const float* __restrict__ wv, const float* __restrict__ wo,
                              const float* __restrict__ w1, const float* __restrict__ w2,
                              __half* __restrict__ Wqkv, __half* __restrict__ Wo,
                              __half* __restrict__ W1,   __half* __restrict__ W2)
{
    int bid = blockIdx.x;
    const float* src; __half* dst; int K, N, local; float scale = 1.0f;
    if (bid < 4096) {
        int m = bid >> 10; local = bid & 1023; K = 1024; N = 1024;
        src = (m == 0) ? wq : (m == 1) ? wk : (m == 2) ? wv : wo;
        dst = (m == 3) ? Wo : Wqkv + m * 1024 * 1024;
        if (m == 0) scale = 0.125f;
    } else if (bid < 8192) {
        local = bid - 4096; K = 1024; N = 4096; src = w1; dst = W1;
    } else {
        local = bid - 8192; K = 4096; N = 1024; src = w2; dst = W2;
    }
    int tilesN = N >> 5;
    int n0 = (local % tilesN) * 32;
    int k0 = (local / tilesN) * 32;

    __shared__ float tile[32][33];
    int tx = threadIdx.x, ty = threadIdx.y;   // 32 x 8
    #pragma unroll
    for (int j = 0; j < 32; j += 8)
        tile[ty + j][tx] = src[(size_t)(k0 + ty + j) * N + n0 + tx];
    __syncthreads();
    #pragma unroll
    for (int j = 0; j < 32; j += 8)
        dst[(size_t)(n0 + ty + j) * K + k0 + tx] = __float2half_rn(tile[tx][ty + j] * scale);
}

__global__ void concat_bias(const float* __restrict__ a, const float* __restrict__ b,
                            const float* __restrict__ c, float* __restrict__ o)
{
    int i = blockIdx.x * blockDim.x + threadIdx.x;
    if (i < QKVN)
        o[i] = (i < DMODEL) ? a[i] * 0.125f
             : (i < 2 * DMODEL ? b[i - DMODEL] : c[i - 2 * DMODEL]);
}

// =======================================================================
// LayerNorm: fp32 in -> fp16 out
// =======================================================================
__global__ void ln_kernel(const float* __restrict__ x,
                          const float* __restrict__ gamma,
                          const float* __restrict__ beta,
                          __half* __restrict__ out)
{
    int row = blockIdx.x;
    int tid = threadIdx.x;
    const float* xr = x + (size_t)row * DMODEL;

    float4 v = *(const float4*)(xr + tid * 4);
    float s  = v.x + v.y + v.z + v.w;
    float sq = v.x*v.x + v.y*v.y + v.z*v.z + v.w*v.w;
    #pragma unroll
    for (int off = 16; off > 0; off >>= 1) {
        s  += __shfl_xor_sync(0xffffffffu, s,  off);
        sq += __shfl_xor_sync(0xffffffffu, sq, off);
    }
    __shared__ float ssum[8], ssq[8];
    int wid = tid >> 5, lane = tid & 31;
    if (lane == 0) { ssum[wid] = s; ssq[wid] = sq; }
    __syncthreads();
    float tot = 0.f, totq = 0.f;
    #pragma unroll
    for (int w = 0; w < 8; w++) { tot += ssum[w]; totq += ssq[w]; }

    const float invN = 1.0f / (float)DMODEL;
    float mean = tot * invN;
    float var  = totq * invN - mean * mean;
    float inv  = rsqrtf(var + 1e-5f);

    float4 g4 = *(const float4*)(gamma + tid * 4);
    float4 b4 = *(const float4*)(beta  + tid * 4);
    uint32_t* op = (uint32_t*)(out + (size_t)row * DMODEL + tid * 4);
    op[0] = f16x2((v.x - mean) * inv * g4.x + b4.x, (v.y - mean) * inv * g4.y + b4.y);
    op[1] = f16x2((v.z - mean) * inv * g4.z + b4.z, (v.w - mean) * inv * g4.w + b4.w);
}

// =======================================================================
// fp16 mma.sync GEMM (identical to round 15 — passing, ~225 TF/s)
// =======================================================================
#define BM 128
#define BN 256
#define BK 32
#define PAD_A 40
#define PAD_B 40
#define A_STG_BYTES (128 * PAD_A * 2)       // 10240
#define B_STG_BYTES (256 * PAD_B * 2)       // 20480
#define STG_BYTES   (A_STG_BYTES + B_STG_BYTES)  // 30720
#define NSTAGE 4
#define GEMM_SMEM (NSTAGE * STG_BYTES)      // 122880 B

__global__ __launch_bounds__(256, 1)
void gemm_mma(const __half* __restrict__ A, const __half* __restrict__ Wt,
              const float* __restrict__ bias, const float* __restrict__ resid,
              float* __restrict__ Cf, __half* __restrict__ Ch,
              int M, int N, int K, int relu)
{
    extern __shared__ char smem_raw[];

    int tid  = threadIdx.x;
    int warp = tid >> 5, lane = tid & 31;
    int wm = warp >> 2;
    int wn = warp & 3;
    int g  = lane >> 2;
    int q  = lane & 3;
    int bm = blockIdx.y * BM;
    int bn = blockIdx.x * BN;

    int s_rowA = tid >> 2;
    int s_kqA  = (tid & 3) * 8;
    int s_rowB = tid >> 2;
    int s_kqB  = (tid & 3) * 8;

    const int KT = K / BK;

    auto stage = [&](int st, int kt) {
        uint32_t aBase = s2u(smem_raw + st * STG_BYTES);
        uint32_t bBase = aBase + A_STG_BYTES;
        const __half* ag = A  + (size_t)(bm + s_rowA) * K + kt * BK + s_kqA;
        const __half* bg = Wt + (size_t)(bn + s_rowB) * K + kt * BK + s_kqB;
        #pragma unroll
        for (int i = 0; i < 2; i++)
            cp16(aBase + ((s_rowA + i * 64) * PAD_A + s_kqA) * 2, ag + (size_t)(i * 64) * K);
        #pragma unroll
        for (int i = 0; i < 4; i++)
            cp16(bBase + ((s_rowB + i * 64) * PAD_B + s_kqB) * 2, bg + (size_t)(i * 64) * K);
    };

    float c[4][8][4];
    #pragma unroll
    for (int mi = 0; mi < 4; mi++)
        #pragma unroll
        for (int ni = 0; ni < 8; ni++)
            #pragma unroll
            for (int r = 0; r < 4; r++) c[mi][ni][r] = 0.f;

    stage(0, 0); CP_COMMIT();
    stage(1, 1); CP_COMMIT();
    stage(2, 2); CP_COMMIT();

    for (int kt = 0; kt < KT; kt++) {
        CP_WAIT(2);
        __syncthreads();

        if (kt + 3 < KT) stage((kt + 3) & 3, kt + 3);
        CP_COMMIT();

        const __half* Af = (const __half*)(smem_raw + (kt & 3) * STG_BYTES)
                         + (wm * 64 + g) * PAD_A + 2 * q;
        const __half* Bf = (const __half*)(smem_raw + (kt & 3) * STG_BYTES + A_STG_BYTES)
                         + (wn * 64 + g) * PAD_B + 2 * q;

        #pragma unroll
        for (int ks = 0; ks < 2; ks++) {
            uint32_t a[4][4], b[8][2];
            #pragma unroll
            for (int mi = 0; mi < 4; mi++) {
                const __half* p = Af + mi * 16 * PAD_A + ks * 16;
                a[mi][0] = *(const uint32_t*)(p);
                a[mi][1] = *(const uint32_t*)(p + 8 * PAD_A);
                a[mi][2] = *(const uint32_t*)(p + 8);
                a[mi][3] = *(const uint32_t*)(p + 8 * PAD_A + 8);
            }
            #pragma unroll
            for (int ni = 0; ni < 8; ni++) {
                const __half* p = Bf + ni * 8 * PAD_B + ks * 16;
                b[ni][0] = *(const uint32_t*)(p);
                b[ni][1] = *(const uint32_t*)(p + 8);
            }
            #pragma unroll
            for (int mi = 0; mi < 4; mi++)
                #pragma unroll
                for (int ni = 0; ni < 8; ni++)
                    mma_f16(c[mi][ni], a[mi][0], a[mi][1], a[mi][2], a[mi][3],
                            b[ni][0], b[ni][1]);
        }
    }

    #pragma unroll
    for (int ni = 0; ni < 8; ni++) {
        int col = bn + wn * 64 + ni * 8 + q * 2;
        float2 bv = *(const float2*)(bias + col);
        #pragma unroll
        for (int mi = 0; mi < 4; mi++) {
            int row = bm + wm * 64 + mi * 16 + g;
            #pragma unroll
            for (int half = 0; half < 2; half++) {
                int r = row + half * 8;
                float ox = c[mi][ni][half * 2 + 0] + bv.x;
                float oy = c[mi][ni][half * 2 + 1] + bv.y;
                if (relu) { ox = fmaxf(ox, 0.f); oy = fmaxf(oy, 0.f); }
                if (Ch) {
                    *(uint32_t*)(Ch + (size_t)r * N + col) = f16x2(ox, oy);
                } else {
                    if (resid) {
                        float2 rv = *(const float2*)(resid + (size_t)r * N + col);
                        ox += rv.x; oy += rv.y;
                    }
                    float2 o; o.x = ox; o.y = oy;
                    *(float2*)(Cf + (size_t)r * N + col) = o;
                }
            }
        }
    }
}

// =======================================================================
// fp16 flash attention — same mainloop as round 15, now 2 CTAs/SM
// (smem 37.1 KB; exposed staging per tile hidden by co-resident CTA).
// =======================================================================
#define PQ 72
#define NEG_BIG (-1e30f)
#define ATTN_SMEM ((128 + 64 + 64) * PQ * 2 + 64 * 4)

__global__ __launch_bounds__(256, 2)
void attn_mma(const __half* __restrict__ QKV, const int* __restrict__ mask,
              __half* __restrict__ O)
{
    extern __shared__ char asm_raw[];
    __half* Qs = (__half*)asm_raw;             // [128][PQ]
    __half* Ks = Qs + 128 * PQ;                // [64][PQ]
    __half* Vt = Ks + 64 * PQ;                 // [64][PQ] (d-major, key minor)
    int*   msk = (int*)(Vt + 64 * PQ);         // [64]

    int tid  = threadIdx.x;
    int warp = tid >> 5, lane = tid & 31;
    int g = lane >> 2, q = lane & 3;
    int row0 = warp * 16;
    int q0 = blockIdx.x * 128;
    int h  = blockIdx.y;
    int b  = blockIdx.z;

    // ---- stage Q via cp.async ----
    {
        int r  = tid >> 1;
        int c0 = (tid & 1) * 32;
        const __half* qp = QKV + (size_t)(b*SEQ + q0 + r) * QKVSTR + h*DHEAD + c0;
        uint32_t qd = s2u(&Qs[r * PQ + c0]);
        #pragma unroll
        for (int i = 0; i < 4; i++)
            cp16(qd + i * 16, qp + i * 8);
    }

    float m_r[2] = {NEG_BIG, NEG_BIG};
    float l_r[2] = {0.f, 0.f};
    float o[8][4];
    #pragma unroll
    for (int nv = 0; nv < 8; nv++)
        #pragma unroll
        for (int r = 0; r < 4; r++) o[nv][r] = 0.f;

    for (int t0 = 0; t0 < SEQ; t0 += 64) {
        // ---- stage K via cp.async ----
        {
            int key = tid >> 2;
            int cb  = (tid & 3) * 8;
            const __half* kp = QKV + (size_t)(b*SEQ + t0 + key) * QKVSTR + DMODEL + h*DHEAD + cb;
            uint32_t kd = s2u(&Ks[key * PQ + cb]);
            cp16(kd,      kp);
            cp16(kd + 64, kp + 32);
        }
        CP_COMMIT();
        // ---- stage V transposed ----
        {
            int key = tid >> 2;
            int db  = (tid & 3) * 16;
            const __half2* vp = (const __half2*)(QKV + (size_t)(b*SEQ + t0 + key) * QKVSTR
                                                 + 2*DMODEL + h*DHEAD + db);
            #pragma unroll
            for (int i = 0; i < 8; i++) {
                __half2 v = vp[i];
                Vt[(db + 2*i + 0) * PQ + key] = __low2half(v);
                Vt[(db + 2*i + 1) * PQ + key] = __high2half(v);
            }
        }
        if (tid < 64) msk[tid] = mask[b*SEQ + t0 + tid];
        CP_WAIT(0);
        __syncthreads();

        // ---- S = Q @ K^T ----
        float sc[8][4];
        #pragma unroll
        for (int nj = 0; nj < 8; nj++)
            #pragma unroll
            for (int r = 0; r < 4; r++) sc[nj][r] = 0.f;

        const __half* Aq = Qs + (row0 + g) * PQ + 2 * q;
        #pragma unroll
        for (int ks = 0; ks < 4; ks++) {
            const __half* p = Aq + ks * 16;
            uint32_t a0 = *(const uint32_t*)(p);
            uint32_t a1 = *(const uint32_t*)(p + 8 * PQ);
            uint32_t a2 = *(const uint32_t*)(p + 8);
            uint32_t a3 = *(const uint32_t*)(p + 8 * PQ + 8);
            #pragma unroll
            for (int nj = 0; nj < 8; nj++) {
                const __half* bp = Ks + (nj * 8 + g) * PQ + ks * 16 + 2 * q;
                mma_f16(sc[nj], a0, a1, a2, a3,
                        *(const uint32_t*)(bp), *(const uint32_t*)(bp + 8));
            }
        }

        // ---- mask ----
        #pragma unroll
        for (int nj = 0; nj < 8; nj++) {
            int c0 = nj * 8 + 2 * q;
            if (msk[c0]     == 0) { sc[nj][0] = NEG_BIG; sc[nj][2] = NEG_BIG; }
            if (msk[c0 + 1] == 0) { sc[nj][1] = NEG_BIG; sc[nj][3] = NEG_BIG; }
        }

        // ---- online softmax ----
        float mx0 = NEG_BIG, mx1 = NEG_BIG;
        #pragma unroll
        for (int nj = 0; nj < 8; nj++) {
            mx0 = fmaxf(mx0, fmaxf(sc[nj][0], sc[nj][1]));
            mx1 = fmaxf(mx1, fmaxf(sc[nj][2], sc[nj][3]));
        }
        mx0 = fmaxf(mx0, __shfl_xor_sync(0xffffffffu, mx0, 1));
        mx0 = fmaxf(mx0, __shfl_xor_sync(0xffffffffu, mx0, 2));
        mx1 = fmaxf(mx1, __shfl_xor_sync(0xffffffffu, mx1, 1));
        mx1 = fmaxf(mx1, __shfl_xor_sync(0xffffffffu, mx1, 2));
        float mn0 = fmaxf(m_r[0], mx0);
        float mn1 = fmaxf(m_r[1], mx1);
        float fac0 = __expf(m_r[0] - mn0);
        float fac1 = __expf(m_r[1] - mn1);

        float sum0 = 0.f, sum1 = 0.f;
        #pragma unroll
        for (int nj = 0; nj < 8; nj++) {
            sc[nj][0] = __expf(sc[nj][0] - mn0);
            sc[nj][1] = __expf(sc[nj][1] - mn0);
            sc[nj][2] = __expf(sc[nj][2] - mn1);
            sc[nj][3] = __expf(sc[nj][3] - mn1);
            sum0 += sc[nj][0] + sc[nj][1];
            sum1 += sc[nj][2] + sc[nj][3];
        }
        sum0 += __shfl_xor_sync(0xffffffffu, sum0, 1);
        sum0 += __shfl_xor_sync(0xffffffffu, sum0, 2);
        sum1 += __shfl_xor_sync(0xffffffffu, sum1, 1);
        sum1 += __shfl_xor_sync(0xffffffffu, sum1, 2);

        l_r[0] = l_r[0] * fac0 + sum0;  m_r[0] = mn0;
        l_r[1] = l_r[1] * fac1 + sum1;  m_r[1] = mn1;

        #pragma unroll
        for (int nv = 0; nv < 8; nv++) {
            o[nv][0] *= fac0; o[nv][1] *= fac0;
            o[nv][2] *= fac1; o[nv][3] *= fac1;
        }

        // ---- O += P @ V (A-frags direct from C-frags) ----
        #pragma unroll
        for (int ks = 0; ks < 4; ks++) {
            uint32_t A0 = f16x2(sc[2*ks][0],   sc[2*ks][1]);
            uint32_t A1 = f16x2(sc[2*ks][2],   sc[2*ks][3]);
            uint32_t A2 = f16x2(sc[2*ks+1][0], sc[2*ks+1][1]);
            uint32_t A3 = f16x2(sc[2*ks+1][2], sc[2*ks+1][3]);
            #pragma unroll
            for (int nv = 0; nv < 8; nv++) {
                const __half* bp = Vt + (nv * 8 + g) * PQ + ks * 16 + 2 * q;
                mma_f16(o[nv], A0, A1, A2, A3,
                        *(const uint32_t*)(bp), *(const uint32_t*)(bp + 8));
            }
        }
        __syncthreads();
    }

    // ---- write ctx (fp16) ----
    float inv0 = 1.0f / l_r[0];
    float inv1 = 1.0f / l_r[1];
    int r0 = q0 + row0 + g;
    int r1 = r0 + 8;
    #pragma unroll
    for (int nv = 0; nv < 8; nv++) {
        int col = h * DHEAD + nv * 8 + 2 * q;
        *(uint32_t*)(O + (size_t)(b*SEQ + r0) * DMODEL + col) = f16x2(o[nv][0]*inv0, o[nv][1]*inv0);
        *(uint32_t*)(O + (size_t)(b*SEQ + r1) * DMODEL + col) = f16x2(o[nv][2]*inv1, o[nv][3]*inv1);
    }
}

// =======================================================================
// launch
// =======================================================================
extern "C" void kernel_launch(void* const* d_in, const int* in_sizes, int n_in,
                              void* d_out, int out_size)
{
    const float* x     = (const float*)d_in[0];
    const int*   mask  = (const int*)  d_in[1];
    const float* wq    = (const float*)d_in[2];
    const float* bq    = (const float*)d_in[3];
    const float* wk    = (const float*)d_in[4];
    const float* bk    = (const float*)d_in[5];
    const float* wv    = (const float*)d_in[6];
    const float* bv    = (const float*)d_in[7];
    const float* wo    = (const float*)d_in[8];
    const float* bo    = (const float*)d_in[9];
    const float* ln1_g = (const float*)d_in[10];
    const float* ln1_b = (const float*)d_in[11];
    const float* ln2_g = (const float*)d_in[12];
    const float* ln2_b = (const float*)d_in[13];
    const float* w1    = (const float*)d_in[14];
    const float* b1    = (const float*)d_in[15];
    const float* w2    = (const float*)d_in[16];
    const float* b2    = (const float*)d_in[17];
    float* out = (float*)d_out;

    float *X2, *Bqkv;
    __half *H, *QKV, *CTX, *FF, *Wqkv, *Wo, *W1, *W2;
    cudaGetSymbolAddress((void**)&H,    g_H);
    cudaGetSymbolAddress((void**)&QKV,  g_QKV);
    cudaGetSymbolAddress((void**)&CTX,  g_CTX);
    cudaGetSymbolAddress((void**)&X2,   g_X2);
    cudaGetSymbolAddress((void**)&FF,   g_FF);
    cudaGetSymbolAddress((void**)&Wqkv, g_Wqkv);
    cudaGetSymbolAddress((void**)&Wo,   g_Wo);
    cudaGetSymbolAddress((void**)&W1,   g_W1);
    cudaGetSymbolAddress((void**)&W2,   g_W2);
    cudaGetSymbolAddress((void**)&Bqkv, g_Bqkv);

    cudaFuncSetAttribute(gemm_mma, cudaFuncAttributeMaxDynamicSharedMemorySize, GEMM_SMEM);
    cudaFuncSetAttribute(attn_mma, cudaFuncAttributeMaxDynamicSharedMemorySize, ATTN_SMEM);

    // fused weight preprocessing (one launch) + bias concat
    transpose_all<<<TRN_BLOCKS, dim3(32, 8)>>>(wq, wk, wv, wo, w1, w2, Wqkv, Wo, W1, W2);
    concat_bias<<<QKVN/256, 256>>>(bq, bk, bv, Bqkv);

    // residual 1: pre-LN attention
    ln_kernel<<<MTOK, 256>>>(x, ln1_g, ln1_b, H);
    gemm_mma<<<dim3(QKVN/BN, MTOK/BM), 256, GEMM_SMEM>>>(H, Wqkv, Bqkv, nullptr,
                                                         nullptr, QKV, MTOK, QKVN, DMODEL, 0);
    attn_mma<<<dim3(SEQ/128, NHEADS, BATCH), 256, ATTN_SMEM>>>(QKV, mask, CTX);
    gemm_mma<<<dim3(DMODEL/BN, MTOK/BM), 256, GEMM_SMEM>>>(CTX, Wo, bo, x,
                                                           X2, nullptr, MTOK, DMODEL, DMODEL, 0);

    // residual 2: pre-LN feed-forward
    ln_kernel<<<MTOK, 256>>>(X2, ln2_g, ln2_b, H);
    gemm_mma<<<dim3(FFDIM/BN, MTOK/BM), 256, GEMM_SMEM>>>(H, W1, b1, nullptr,
                                                          nullptr, FF, MTOK, FFDIM, DMODEL, 1);
    gemm_mma<<<dim3(DMODEL/BN, MTOK/BM), 256, GEMM_SMEM>>>(FF, W2, b2, X2,
                                                           out, nullptr, MTOK, DMODEL, FFDIM, 0);
}

// round 17
// speedup vs baseline: 1.6833x; 1.0218x over previous
#include <cuda_runtime.h>
#include <cuda_bf16.h>
#include <cuda_fp16.h>
#include <math.h>
#include <stdint.h>

// ---------------- problem constants ----------------
#define BATCH   2
#define SEQ     2048
#define DMODEL  1024
#define NHEADS  16
#define DHEAD   64
#define FFDIM   4096
#define MTOK    (BATCH * SEQ)          // 4096 token rows
#define QKVN    (3 * DMODEL)           // 3072
#define QKVSTR  3072

// ---------------- scratch (device globals; no allocation) ----------------
__device__ __half g_H   [MTOK * DMODEL];
__device__ __half g_QKV [MTOK * QKVN];
__device__ __half g_CTX [MTOK * DMODEL];
__device__ float  g_X2  [MTOK * DMODEL];
__device__ __half g_FF  [MTOK * FFDIM];
__device__ __half g_Wqkv[QKVN  * DMODEL];
__device__ __half g_Wo  [DMODEL * DMODEL];
__device__ __half g_W1  [FFDIM * DMODEL];
__device__ __half g_W2  [DMODEL * FFDIM];
__device__ float  g_Bqkv[QKVN];

__device__ __forceinline__ uint32_t s2u(const void* p) {
    uint32_t a;
    asm("{ .reg .u64 t; cvta.to.shared.u64 t, %1; cvt.u32.u64 %0, t; }" : "=r"(a) : "l"(p));
    return a;
}
__device__ __forceinline__ uint32_t f16x2(float lo, float hi) {
    uint32_t r; asm("cvt.rn.f16x2.f32 %0, %1, %2;" : "=r"(r) : "f"(hi), "f"(lo)); return r;
}
__device__ __forceinline__ void cp16(uint32_t dst, const void* src) {
    asm volatile("cp.async.cg.shared.global [%0], [%1], 16;" :: "r"(dst), "l"(src));
}
#define CP_COMMIT() asm volatile("cp.async.commit_group;" ::: "memory")
#define CP_WAIT(n)  asm volatile("cp.async.wait_group %0;" :: "n"(n) : "memory")

__device__ __forceinline__ void mma_f16(float c[4], uint32_t a0, uint32_t a1,
                                        uint32_t a2, uint32_t a3,
                                        uint32_t b0, uint32_t b1)
{
    asm volatile(
        "mma.sync.aligned.m16n8k16.row.col.f32.f16.f16.f32 "
        "{%0,%1,%2,%3}, {%4,%5,%6,%7}, {%8,%9}, {%0,%1,%2,%3};"
        : "+f"(c[0]), "+f"(c[1]), "+f"(c[2]), "+f"(c[3])
        : "r"(a0), "r"(a1), "r"(a2), "r"(a3), "r"(b0), "r"(b1));
}

// =======================================================================
// fused weight transpose + fp16 convert (+scale) — ONE launch (round-16)
// =======================================================================
#define TRN_BLOCKS 12288

__global__ void transpose_all(const float* __restrict__ wq, const float* __restrict__ wk,
                              const float* __restrict__ wv, const float* __restrict__ wo,
                              const float* __restrict__ w1, const float* __restrict__ w2,
                              __half* __restrict__ Wqkv, __half* __restrict__ Wo,
                              __half* __restrict__ W1,   __half* __restrict__ W2)
{
    int bid = blockIdx.x;
    const float* src; __half* dst; int K, N, local; float scale = 1.0f;
    if (bid < 4096) {
        int m = bid >> 10; local = bid & 1023; K = 1024; N = 1024;
        src = (m == 0) ? wq : (m == 1) ? wk : (m == 2) ? wv : wo;
        dst = (m == 3) ? Wo : Wqkv + m * 1024 * 1024;
        if (m == 0) scale = 0.125f;
    } else if (bid < 8192) {
        local = bid - 4096; K = 1024; N = 4096; src = w1; dst = W1;
    } else {
        local = bid - 8192; K = 4096; N = 1024; src = w2; dst = W2;
    }
    int tilesN = N >> 5;
    int n0 = (local % tilesN) * 32;
    int k0 = (local / tilesN) * 32;

    __shared__ float tile[32][33];
    int tx = threadIdx.x, ty = threadIdx.y;
    #pragma unroll
    for (int j = 0; j < 32; j += 8)
        tile[ty + j][tx] = src[(size_t)(k0 + ty + j) * N + n0 + tx];
    __syncthreads();
    #pragma unroll
    for (int j = 0; j < 32; j += 8)
        dst[(size_t)(n0 + ty + j) * K + k0 + tx] = __float2half_rn(tile[tx][ty + j] * scale);
}

__global__ void concat_bias(const float* __restrict__ a, const float* __restrict__ b,
                            const float* __restrict__ c, float* __restrict__ o)
{
    int i = blockIdx.x * blockDim.x + threadIdx.x;
    if (i < QKVN)
        o[i] = (i < DMODEL) ? a[i] * 0.125f
             : (i < 2 * DMODEL ? b[i - DMODEL] : c[i - 2 * DMODEL]);
}

// =======================================================================
// LayerNorm: fp32 in -> fp16 out (round-15)
// =======================================================================
__global__ void ln_kernel(const float* __restrict__ x,
                          const float* __restrict__ gamma,
                          const float* __restrict__ beta,
                          __half* __restrict__ out)
{
    int row = blockIdx.x;
    int tid = threadIdx.x;
    const float* xr = x + (size_t)row * DMODEL;

    float4 v = *(const float4*)(xr + tid * 4);
    float s  = v.x + v.y + v.z + v.w;
    float sq = v.x*v.x + v.y*v.y + v.z*v.z + v.w*v.w;
    #pragma unroll
    for (int off = 16; off > 0; off >>= 1) {
        s  += __shfl_xor_sync(0xffffffffu, s,  off);
        sq += __shfl_xor_sync(0xffffffffu, sq, off);
    }
    __shared__ float ssum[8], ssq[8];
    int wid = tid >> 5, lane = tid & 31;
    if (lane == 0) { ssum[wid] = s; ssq[wid] = sq; }
    __syncthreads();
    float tot = 0.f, totq = 0.f;
    #pragma unroll
    for (int w = 0; w < 8; w++) { tot += ssum[w]; totq += ssq[w]; }

    const float invN = 1.0f / (float)DMODEL;
    float mean = tot * invN;
    float var  = totq * invN - mean * mean;
    float inv  = rsqrtf(var + 1e-5f);

    float4 g4 = *(const float4*)(gamma + tid * 4);
    float4 b4 = *(const float4*)(beta  + tid * 4);
    uint32_t* op = (uint32_t*)(out + (size_t)row * DMODEL + tid * 4);
    op[0] = f16x2((v.x - mean) * inv * g4.x + b4.x, (v.y - mean) * inv * g4.y + b4.y);
    op[1] = f16x2((v.z - mean) * inv * g4.z + b4.z, (v.w - mean) * inv * g4.w + b4.w);
}

// =======================================================================
// fp16 mma.sync GEMM — 128x128 tile, warp tile 64x32, 2 CTAs/SM.
// 4-stage cp.async pipeline, ONE __syncthreads per K-iteration.
// =======================================================================
#define BM 128
#define BN 128
#define BK 32
#define PAD_A 40
#define PAD_B 40
#define A_STG_BYTES (128 * PAD_A * 2)       // 10240
#define B_STG_BYTES (128 * PAD_B * 2)       // 10240
#define STG_BYTES   (A_STG_BYTES + B_STG_BYTES)  // 20480
#define NSTAGE 4
#define GEMM_SMEM (NSTAGE * STG_BYTES)      // 81920 B -> 2 CTAs/SM

__global__ __launch_bounds__(256, 2)
void gemm_mma(const __half* __restrict__ A, const __half* __restrict__ Wt,
              const float* __restrict__ bias, const float* __restrict__ resid,
              float* __restrict__ Cf, __half* __restrict__ Ch,
              int M, int N, int K, int relu)
{
    extern __shared__ char smem_raw[];

    int tid  = threadIdx.x;
    int warp = tid >> 5, lane = tid & 31;
    int wm = warp >> 2;          // 0..1 -> 64-row group
    int wn = warp & 3;           // 0..3 -> 32-col group
    int g  = lane >> 2;
    int q  = lane & 3;
    int bm = blockIdx.y * BM;
    int bn = blockIdx.x * BN;

    // staging: 128 rows x 64B = 512 chunks per operand, 2/thread each
    int s_row = tid >> 2;              // 0..63 (+64)
    int s_kq  = (tid & 3) * 8;         // halves

    const int KT = K / BK;

    auto stage = [&](int st, int kt) {
        uint32_t aBase = s2u(smem_raw + st * STG_BYTES);
        uint32_t bBase = aBase + A_STG_BYTES;
        const __half* ag = A  + (size_t)(bm + s_row) * K + kt * BK + s_kq;
        const __half* bg = Wt + (size_t)(bn + s_row) * K + kt * BK + s_kq;
        #pragma unroll
        for (int i = 0; i < 2; i++) {
            cp16(aBase + ((s_row + i * 64) * PAD_A + s_kq) * 2, ag + (size_t)(i * 64) * K);
            cp16(bBase + ((s_row + i * 64) * PAD_B + s_kq) * 2, bg + (size_t)(i * 64) * K);
        }
    };

    float c[4][4][4];
    #pragma unroll
    for (int mi = 0; mi < 4; mi++)
        #pragma unroll
        for (int ni = 0; ni < 4; ni++)
            #pragma unroll
            for (int r = 0; r < 4; r++) c[mi][ni][r] = 0.f;

    stage(0, 0); CP_COMMIT();
    stage(1, 1); CP_COMMIT();
    stage(2, 2); CP_COMMIT();

    for (int kt = 0; kt < KT; kt++) {
        CP_WAIT(2);
        __syncthreads();

        if (kt + 3 < KT) stage((kt + 3) & 3, kt + 3);
        CP_COMMIT();

        const __half* Af = (const __half*)(smem_raw + (kt & 3) * STG_BYTES)
                         + (wm * 64 + g) * PAD_A + 2 * q;
        const __half* Bf = (const __half*)(smem_raw + (kt & 3) * STG_BYTES + A_STG_BYTES)
                         + (wn * 32 + g) * PAD_B + 2 * q;

        #pragma unroll
        for (int ks = 0; ks < 2; ks++) {
            uint32_t a[4][4], b[4][2];
            #pragma unroll
            for (int mi = 0; mi < 4; mi++) {
                const __half* p = Af + mi * 16 * PAD_A + ks * 16;
                a[mi][0] = *(const uint32_t*)(p);
                a[mi][1] = *(const uint32_t*)(p + 8 * PAD_A);
                a[mi][2] = *(const uint32_t*)(p + 8);
                a[mi][3] = *(const uint32_t*)(p + 8 * PAD_A + 8);
            }
            #pragma unroll
            for (int ni = 0; ni < 4; ni++) {
                const __half* p = Bf + ni * 8 * PAD_B + ks * 16;
                b[ni][0] = *(const uint32_t*)(p);
                b[ni][1] = *(const uint32_t*)(p + 8);
            }
            #pragma unroll
            for (int mi = 0; mi < 4; mi++)
                #pragma unroll
                for (int ni = 0; ni < 4; ni++)
                    mma_f16(c[mi][ni], a[mi][0], a[mi][1], a[mi][2], a[mi][3],
                            b[ni][0], b[ni][1]);
        }
    }

    // ---- epilogue ----
    #pragma unroll
    for (int ni = 0; ni < 4; ni++) {
        int col = bn + wn * 32 + ni * 8 + q * 2;
        float2 bv = *(const float2*)(bias + col);
        #pragma unroll
        for (int mi = 0; mi < 4; mi++) {
            int row = bm + wm * 64 + mi * 16 + g;
            #pragma unroll
            for (int half = 0; half < 2; half++) {
                int r = row + half * 8;
                float ox = c[mi][ni][half * 2 + 0] + bv.x;
                float oy = c[mi][ni][half * 2 + 1] + bv.y;
                if (relu) { ox = fmaxf(ox, 0.f); oy = fmaxf(oy, 0.f); }
                if (Ch) {
                    *(uint32_t*)(Ch + (size_t)r * N + col) = f16x2(ox, oy);
                } else {
                    if (resid) {
                        float2 rv = *(const float2*)(resid + (size_t)r * N + col);
                        ox += rv.x; oy += rv.y;
                    }
                    float2 o; o.x = ox; o.y = oy;
                    *(float2*)(Cf + (size_t)r * N + col) = o;
                }
            }
        }
    }
}

// =======================================================================
// fp16 flash attention (round-16 version — passing, occ 2)
// =======================================================================
#define PQ 72
#define NEG_BIG (-1e30f)
#define ATTN_SMEM ((128 + 64 + 64) * PQ * 2 + 64 * 4)

__global__ __launch_bounds__(256, 2)
void attn_mma(const __half* __restrict__ QKV, const int* __restrict__ mask,
              __half* __restrict__ O)
{
    extern __shared__ char asm_raw[];
    __half* Qs = (__half*)asm_raw;
    __half* Ks = Qs + 128 * PQ;
    __half* Vt = Ks + 64 * PQ;
    int*   msk = (int*)(Vt + 64 * PQ);

    int tid  = threadIdx.x;
    int warp = tid >> 5, lane = tid & 31;
    int g = lane >> 2, q = lane & 3;
    int row0 = warp * 16;
    int q0 = blockIdx.x * 128;
    int h  = blockIdx.y;
    int b  = blockIdx.z;

    {
        int r  = tid >> 1;
        int c0 = (tid & 1) * 32;
        const __half* qp = QKV + (size_t)(b*SEQ + q0 + r) * QKVSTR + h*DHEAD + c0;
        uint32_t qd = s2u(&Qs[r * PQ + c0]);
        #pragma unroll
        for (int i = 0; i < 4; i++)
            cp16(qd + i * 16, qp + i * 8);
    }

    float m_r[2] = {NEG_BIG, NEG_BIG};
    float l_r[2] = {0.f, 0.f};
    float o[8][4];
    #pragma unroll
    for (int nv = 0; nv < 8; nv++)
        #pragma unroll
        for (int r = 0; r < 4; r++) o[nv][r] = 0.f;

    for (int t0 = 0; t0 < SEQ; t0 += 64) {
        {
            int key = tid >> 2;
            int cb  = (tid & 3) * 8;
            const __half* kp = QKV + (size_t)(b*SEQ + t0 + key) * QKVSTR + DMODEL + h*DHEAD + cb;
            uint32_t kd = s2u(&Ks[key * PQ + cb]);
            cp16(kd,      kp);
            cp16(kd + 64, kp + 32);
        }
        CP_COMMIT();
        {
            int key = tid >> 2;
            int db  = (tid & 3) * 16;
            const __half2* vp = (const __half2*)(QKV + (size_t)(b*SEQ + t0 + key) * QKVSTR
                                                 + 2*DMODEL + h*DHEAD + db);
            #pragma unroll
            for (int i = 0; i < 8; i++) {
                __half2 v = vp[i];
                Vt[(db + 2*i + 0) * PQ + key] = __low2half(v);
                Vt[(db + 2*i + 1) * PQ + key] = __high2half(v);
            }
        }
        if (tid < 64) msk[tid] = mask[b*SEQ + t0 + tid];
        CP_WAIT(0);
        __syncthreads();

        float sc[8][4];
        #pragma unroll
        for (int nj = 0; nj < 8; nj++)
            #pragma unroll
            for (int r = 0; r < 4; r++) sc[nj][r] = 0.f;

        const __half* Aq = Qs + (row0 + g) * PQ + 2 * q;
        #pragma unroll
        for (int ks = 0; ks < 4; ks++) {
            const __half* p = Aq + ks * 16;
            uint32_t a0 = *(const uint32_t*)(p);
            uint32_t a1 = *(const uint32_t*)(p + 8 * PQ);
            uint32_t a2 = *(const uint32_t*)(p + 8);
            uint32_t a3 = *(const uint32_t*)(p + 8 * PQ + 8);
            #pragma unroll
            for (int nj = 0; nj < 8; nj++) {
                const __half* bp = Ks + (nj * 8 + g) * PQ + ks * 16 + 2 * q;
                mma_f16(sc[nj], a0, a1, a2, a3,
                        *(const uint32_t*)(bp), *(const uint32_t*)(bp + 8));
            }
        }

        #pragma unroll
        for (int nj = 0; nj < 8; nj++) {
            int c0 = nj * 8 + 2 * q;
            if (msk[c0]     == 0) { sc[nj][0] = NEG_BIG; sc[nj][2] = NEG_BIG; }
            if (msk[c0 + 1] == 0) { sc[nj][1] = NEG_BIG; sc[nj][3] = NEG_BIG; }
        }

        float mx0 = NEG_BIG, mx1 = NEG_BIG;
        #pragma unroll
        for (int nj = 0; nj < 8; nj++) {
            mx0 = fmaxf(mx0, fmaxf(sc[nj][0], sc[nj][1]));
            mx1 = fmaxf(mx1, fmaxf(sc[nj][2], sc[nj][3]));
        }
        mx0 = fmaxf(mx0, __shfl_xor_sync(0xffffffffu, mx0, 1));
        mx0 = fmaxf(mx0, __shfl_xor_sync(0xffffffffu, mx0, 2));
        mx1 = fmaxf(mx1, __shfl_xor_sync(0xffffffffu, mx1, 1));
        mx1 = fmaxf(mx1, __shfl_xor_sync(0xffffffffu, mx1, 2));
        float mn0 = fmaxf(m_r[0], mx0);
        float mn1 = fmaxf(m_r[1], mx1);
        float fac0 = __expf(m_r[0] - mn0);
        float fac1 = __expf(m_r[1] - mn1);

        float sum0 = 0.f, sum1 = 0.f;
        #pragma unroll
        for (int nj = 0; nj < 8; nj++) {
            sc[nj][0] = __expf(sc[nj][0] - mn0);
            sc[nj][1] = __expf(sc[nj][1] - mn0);
            sc[nj][2] = __expf(sc[nj][2] - mn1);
            sc[nj][3] = __expf(sc[nj][3] - mn1);
            sum0 += sc[nj][0] + sc[nj][1];
            sum1 += sc[nj][2] + sc[nj][3];
        }
        sum0 += __shfl_xor_sync(0xffffffffu, sum0, 1);
        sum0 += __shfl_xor_sync(0xffffffffu, sum0, 2);
        sum1 += __shfl_xor_sync(0xffffffffu, sum1, 1);
        sum1 += __shfl_xor_sync(0xffffffffu, sum1, 2);

        l_r[0] = l_r[0] * fac0 + sum0;  m_r[0] = mn0;
        l_r[1] = l_r[1] * fac1 + sum1;  m_r[1] = mn1;

        #pragma unroll
        for (int nv = 0; nv < 8; nv++) {
            o[nv][0] *= fac0; o[nv][1] *= fac0;
            o[nv][2] *= fac1; o[nv][3] *= fac1;
        }

        #pragma unroll
        for (int ks = 0; ks < 4; ks++) {
            uint32_t A0 = f16x2(sc[2*ks][0],   sc[2*ks][1]);
            uint32_t A1 = f16x2(sc[2*ks][2],   sc[2*ks][3]);
            uint32_t A2 = f16x2(sc[2*ks+1][0], sc[2*ks+1][1]);
            uint32_t A3 = f16x2(sc[2*ks+1][2], sc[2*ks+1][3]);
            #pragma unroll
            for (int nv = 0; nv < 8; nv++) {
                const __half* bp = Vt + (nv * 8 + g) * PQ + ks * 16 + 2 * q;
                mma_f16(o[nv], A0, A1, A2, A3,
                        *(const uint32_t*)(bp), *(const uint32_t*)(bp + 8));
            }
        }
        __syncthreads();
    }

    float inv0 = 1.0f / l_r[0];
    float inv1 = 1.0f / l_r[1];
    int r0 = q0 + row0 + g;
    int r1 = r0 + 8;
    #pragma unroll
    for (int nv = 0; nv < 8; nv++) {
        int col = h * DHEAD + nv * 8 + 2 * q;
        *(uint32_t*)(O + (size_t)(b*SEQ + r0) * DMODEL + col) = f16x2(o[nv][0]*inv0, o[nv][1]*inv0);
        *(uint32_t*)(O + (size_t)(b*SEQ + r1) * DMODEL + col) = f16x2(o[nv][2]*inv1, o[nv][3]*inv1);
    }
}

// =======================================================================
// launch
// =======================================================================
extern "C" void kernel_launch(void* const* d_in, const int* in_sizes, int n_in,
                              void* d_out, int out_size)
{
    const float* x     = (const float*)d_in[0];
    const int*   mask  = (const int*)  d_in[1];
    const float* wq    = (const float*)d_in[2];
    const float* bq    = (const float*)d_in[3];
    const float* wk    = (const float*)d_in[4];
    const float* bk    = (const float*)d_in[5];
    const float* wv    = (const float*)d_in[6];
    const float* bv    = (const float*)d_in[7];
    const float* wo    = (const float*)d_in[8];
    const float* bo    = (const float*)d_in[9];
    const float* ln1_g = (const float*)d_in[10];
    const float* ln1_b = (const float*)d_in[11];
    const float* ln2_g = (const float*)d_in[12];
    const float* ln2_b = (const float*)d_in[13];
    const float* w1    = (const float*)d_in[14];
    const float* b1    = (const float*)d_in[15];
    const float* w2    = (const float*)d_in[16];
    const float* b2    = (const float*)d_in[17];
    float* out = (float*)d_out;

    float *X2, *Bqkv;
    __half *H, *QKV, *CTX, *FF, *Wqkv, *Wo, *W1, *W2;
    cudaGetSymbolAddress((void**)&H,    g_H);
    cudaGetSymbolAddress((void**)&QKV,  g_QKV);
    cudaGetSymbolAddress((void**)&CTX,  g_CTX);
    cudaGetSymbolAddress((void**)&X2,   g_X2);
    cudaGetSymbolAddress((void**)&FF,   g_FF);
    cudaGetSymbolAddress((void**)&Wqkv, g_Wqkv);
    cudaGetSymbolAddress((void**)&Wo,   g_Wo);
    cudaGetSymbolAddress((void**)&W1,   g_W1);
    cudaGetSymbolAddress((void**)&W2,   g_W2);
    cudaGetSymbolAddress((void**)&Bqkv, g_Bqkv);

    cudaFuncSetAttribute(gemm_mma, cudaFuncAttributeMaxDynamicSharedMemorySize, GEMM_SMEM);
    cudaFuncSetAttribute(attn_mma, cudaFuncAttributeMaxDynamicSharedMemorySize, ATTN_SMEM);

    transpose_all<<<TRN_BLOCKS, dim3(32, 8)>>>(wq, wk, wv, wo, w1, w2, Wqkv, Wo, W1, W2);
    concat_bias<<<QKVN/256, 256>>>(bq, bk, bv, Bqkv);

    // residual 1: pre-LN attention
    ln_kernel<<<MTOK, 256>>>(x, ln1_g, ln1_b, H);
    gemm_mma<<<dim3(QKVN/BN, MTOK/BM), 256, GEMM_SMEM>>>(H, Wqkv, Bqkv, nullptr,
                                                         nullptr, QKV, MTOK, QKVN, DMODEL, 0);
    attn_mma<<<dim3(SEQ/128, NHEADS, BATCH), 256, ATTN_SMEM>>>(QKV, mask, CTX);
    gemm_mma<<<dim3(DMODEL/BN, MTOK/BM), 256, GEMM_SMEM>>>(CTX, Wo, bo, x,
                                                           X2, nullptr, MTOK, DMODEL, DMODEL, 0);

    // residual 2: pre-LN feed-forward
    ln_kernel<<<MTOK, 256>>>(X2, ln2_g, ln2_b, H);
    gemm_mma<<<dim3(FFDIM/BN, MTOK/BM), 256, GEMM_SMEM>>>(H, W1, b1, nullptr,
                                                          nullptr, FF, MTOK, FFDIM, DMODEL, 1);
    gemm_mma<<<dim3(DMODEL/BN, MTOK/BM), 256, GEMM_SMEM>>>(FF, W2, b2, X2,
                                                           out, nullptr, MTOK, DMODEL, FFDIM, 0);
}